// round 2
// baseline (speedup 1.0000x reference)
#include <cuda_runtime.h>
#include <cuda_bf16.h>
#include <math.h>

// Problem dims (fixed)
#define BB   2
#define SQ   512
#define SKK  512
#define EE   512
#define HH   256
#define MR   1024            // B*SQ = B*SK
#define NTOT (BB*SQ*SKK)     // 524288

// ---------------- scratch (device globals; no allocation allowed) -------------
__device__ float g_qf [MR*HH];
__device__ float g_kf [MR*HH];
__device__ float g_qp [MR*HH];
__device__ float g_vq [MR*HH];
__device__ float g_kpT[HH*MR];   // [H][B*SK]
__device__ float g_vkT[HH*MR];   // [H][B*SK]

// ---------------- helpers -----------------------------------------------------
__device__ __forceinline__ unsigned smem_u32(const void* p) {
    return (unsigned)__cvta_generic_to_shared(p);
}
__device__ __forceinline__ void unpack2(unsigned long long v, float& lo, float& hi) {
    asm("mov.b64 {%0, %1}, %2;" : "=f"(lo), "=f"(hi) : "l"(v));
}
__device__ __forceinline__ unsigned long long pack_dup(float a) {
    unsigned long long r;
    asm("mov.b64 %0, {%1, %1};" : "=l"(r) : "f"(a));
    return r;
}
__device__ __forceinline__ void ffma2(unsigned long long& acc, unsigned long long a, unsigned long long b) {
    asm("fma.rn.f32x2 %0, %1, %2, %0;" : "+l"(acc) : "l"(a), "l"(b));
}
__device__ __forceinline__ float softplusf(float x) {
    if (x > 20.f) return x;
    return log1pf(expf(x));
}

// ---------------- prologue: generic 1024xN projection GEMM --------------------
// C[r][n] = act( sum_k A[r][k] * W[wrow0+k][n] + bias[n] ),  N = 256 fixed
// trans: store C_T[n*ldT + r] instead.
__global__ __launch_bounds__(256)
void proj_kernel(const float* __restrict__ A, const float* __restrict__ W,
                 const float* __restrict__ bias, float* __restrict__ C,
                 int K, int wrow0, int doRelu, int doTrans, int ldT)
{
    __shared__ float As[16][36];
    __shared__ float Ws[16][68];
    const int tid = threadIdx.x;
    const int m0  = blockIdx.y * 32;
    const int n0  = blockIdx.x * 64;
    const int ty  = tid >> 4, tx = tid & 15;

    float acc[2][4] = {};
    const int nch = K >> 4;
    for (int ch = 0; ch < nch; ch++) {
        const int kc = ch << 4;
        __syncthreads();
        {   // A chunk: 32 rows x 16 k
            int e = tid;        int m = e >> 4, kk = e & 15;
            As[kk][m] = A[(m0 + m) * K + kc + kk];
            e = tid + 256;      m = e >> 4;     kk = e & 15;
            As[kk][m] = A[(m0 + m) * K + kc + kk];
        }
        #pragma unroll
        for (int i = 0; i < 4; i++) {   // W chunk: 16 k x 64 n
            int e = tid + (i << 8);
            int kk = e >> 6, n = e & 63;
            Ws[kk][n] = W[(wrow0 + kc + kk) * 256 + n0 + n];
        }
        __syncthreads();
        #pragma unroll
        for (int kk = 0; kk < 16; kk++) {
            float a0 = As[kk][ty * 2], a1 = As[kk][ty * 2 + 1];
            float w0 = Ws[kk][tx * 4], w1 = Ws[kk][tx * 4 + 1];
            float w2 = Ws[kk][tx * 4 + 2], w3 = Ws[kk][tx * 4 + 3];
            acc[0][0] = fmaf(a0, w0, acc[0][0]);
            acc[0][1] = fmaf(a0, w1, acc[0][1]);
            acc[0][2] = fmaf(a0, w2, acc[0][2]);
            acc[0][3] = fmaf(a0, w3, acc[0][3]);
            acc[1][0] = fmaf(a1, w0, acc[1][0]);
            acc[1][1] = fmaf(a1, w1, acc[1][1]);
            acc[1][2] = fmaf(a1, w2, acc[1][2]);
            acc[1][3] = fmaf(a1, w3, acc[1][3]);
        }
    }
    #pragma unroll
    for (int i = 0; i < 2; i++) {
        const int r = m0 + ty * 2 + i;
        #pragma unroll
        for (int j = 0; j < 4; j++) {
            const int n = n0 + tx * 4 + j;
            float v = acc[i][j] + (bias ? bias[n] : 0.f);
            if (doRelu) v = fmaxf(v, 0.f);
            if (doTrans) C[n * ldT + r] = v;
            else         C[r * 256 + n] = v;
        }
    }
}

// ---------------- main pairwise-MLP kernel ------------------------------------
// block = (b, q, 64-key tile). 256 threads. SMEM buf holds h0 (then h1)
// transposed: buf[feature][key], row stride 68 floats.

__device__ __forceinline__ void issue_chunk(const float* __restrict__ Wg, int c, int s,
                                            unsigned wbuf_u32, int tid)
{
    #pragma unroll
    for (int i = 0; i < 2; i++) {
        int e  = tid + i * 256;            // 0..511
        int kk = e >> 6;                   // 0..7
        int n4 = (e & 63) << 2;            // 0..252 step 4
        unsigned dst = wbuf_u32 + ((unsigned)(s * 2048 + kk * 256 + n4) << 2);
        const float* src = Wg + (c * 8 + kk) * 256 + n4;
        asm volatile("cp.async.cg.shared.global [%0], [%1], 16;" :: "r"(dst), "l"(src));
    }
    asm volatile("cp.async.commit_group;" ::: "memory");
}

__device__ __forceinline__ void gemm_tile(const float* __restrict__ Wg,
                                          const float* __restrict__ bs,
                                          const float* __restrict__ buf,
                                          const float* __restrict__ wbuf,
                                          unsigned wbuf_u32,
                                          int m0, int n0, int tid, bool pre0,
                                          unsigned long long (&acc)[8][4])
{
    // init accumulators with bias pairs (bias pre-added: epilogue is just relu)
    unsigned long long bias2[4];
    #pragma unroll
    for (int j = 0; j < 4; j++)
        bias2[j] = *reinterpret_cast<const unsigned long long*>(&bs[n0 + 2 * j]);
    #pragma unroll
    for (int i = 0; i < 8; i++)
        #pragma unroll
        for (int j = 0; j < 4; j++) acc[i][j] = bias2[j];

    if (!pre0) issue_chunk(Wg, 0, 0, wbuf_u32, tid);

    #pragma unroll 1
    for (int c = 0; c < 32; c++) {
        asm volatile("cp.async.wait_group 0;" ::: "memory");
        __syncthreads();
        if (c < 31) issue_chunk(Wg, c + 1, (c + 1) & 1, wbuf_u32, tid);
        const float* wr = wbuf + (c & 1) * 2048;
        const float* br = buf + (c * 8) * 68 + m0;
        #pragma unroll
        for (int kk = 0; kk < 8; kk++) {
            float4 a0 = *reinterpret_cast<const float4*>(br + kk * 68);
            float4 a1 = *reinterpret_cast<const float4*>(br + kk * 68 + 4);
            const unsigned long long* wp =
                reinterpret_cast<const unsigned long long*>(wr + kk * 256 + n0);
            unsigned long long bb0 = wp[0], bb1 = wp[1], bb2 = wp[2], bb3 = wp[3];
            float av[8] = {a0.x, a0.y, a0.z, a0.w, a1.x, a1.y, a1.z, a1.w};
            #pragma unroll
            for (int i = 0; i < 8; i++) {
                unsigned long long ad = pack_dup(av[i]);
                ffma2(acc[i][0], ad, bb0);
                ffma2(acc[i][1], ad, bb1);
                ffma2(acc[i][2], ad, bb2);
                ffma2(acc[i][3], ad, bb3);
            }
        }
    }
}

__global__ __launch_bounds__(256, 2)
void pair_mlp_kernel(const float* __restrict__ W2, const float* __restrict__ b2,
                     const float* __restrict__ W3, const float* __restrict__ b3,
                     const float* __restrict__ Wf, const float* __restrict__ bfp,
                     const float* __restrict__ b1, const float* __restrict__ bv1,
                     const float* __restrict__ Wv2, const float* __restrict__ bv2,
                     float* __restrict__ out)
{
    extern __shared__ float sm[];
    float* buf  = sm;                  // 256*68 = 17408
    float* wbuf = sm + 256 * 68;       // 2*8*256 = 4096
    float* qpb  = wbuf + 4096;         // 256
    float* vqb  = qpb + 256;           // 256
    float* b2s  = vqb + 256;           // 256
    float* b3s  = b2s + 256;           // 256
    float* wfs  = b3s + 256;           // 256
    float* wv2s = wfs + 256;           // 256
    float* red  = wv2s + 256;          // 256
    float* vred = red + 256;           // 256

    const int tid = threadIdx.x;
    const int bid = blockIdx.x;
    const int kt  = bid & 7;
    const int q   = (bid >> 3) & 511;
    const int b   = bid >> 12;
    const int k0  = kt << 6;

    const int warp  = tid >> 5;
    const int lane  = tid & 31;
    const int warpm = warp >> 2;           // 0..1
    const int warpn = warp & 3;            // 0..3
    const int lm    = lane >> 3;           // 0..3
    const int ln    = lane & 7;            // 0..7
    const int m0    = warpm * 32 + lm * 8; // key-row base
    const int n0    = warpn * 64 + ln * 8; // feature-col base

    const unsigned wbuf_u32 = smem_u32(wbuf);

    // prefetch W2 chunk 0 immediately (overlaps the setup phases)
    issue_chunk(W2, 0, 0, wbuf_u32, tid);

    // ---- phase 1: vector loads ----
    {
        const int r = (b * SQ + q) * HH + tid;
        qpb[tid]  = g_qp[r] + b1[tid];
        vqb[tid]  = g_vq[r] + bv1[tid];
        b2s[tid]  = b2[tid];
        b3s[tid]  = b3[tid];
        wfs[tid]  = Wf[tid];
        wv2s[tid] = Wv2[tid];
    }
    __syncthreads();

    // ---- phase 2: variance partials + h0 build ----
    {
        const int p = tid >> 6;              // 0..3
        const int m = tid & 63;
        const int rowb = b * SKK + k0 + m;
        float vacc = 0.f;
        #pragma unroll 8
        for (int jj = 0; jj < 64; jj++) {
            const int j = (p << 6) + jj;
            float t = vqb[j] + g_vkT[j * MR + rowb];
            vacc = fmaf(fmaxf(t, 0.f), wv2s[j], vacc);
        }
        vred[(m << 2) + p] = vacc;
    }
    {
        const int base = b * SKK + k0;
        #pragma unroll 8
        for (int e = tid; e < 64 * HH; e += 256) {
            const int j = e >> 6, m = e & 63;
            float t = qpb[j] + g_kpT[j * MR + base + m];
            buf[j * 68 + m] = fmaxf(t, 0.f);
        }
    }
    __syncthreads();

    const int lbase = (b * SQ + q) * SKK + k0;

    // ---- phase 3: variance finalize ----
    if (tid < 64) {
        float s = vred[tid * 4] + vred[tid * 4 + 1] + vred[tid * 4 + 2] + vred[tid * 4 + 3]
                  + bv2[0];
        out[NTOT + lbase + tid] = softplusf(s);
    }

    // ---- GEMM 1: h1 = relu(h0 @ W2 + b2) ----
    unsigned long long acc[8][4];
    gemm_tile(W2, b2s, buf, wbuf, wbuf_u32, m0, n0, tid, true, acc);
    __syncthreads();   // all readers of h0 in buf are done

    // write h1 back into buf (transposed: buf[feature][key])
    #pragma unroll
    for (int j = 0; j < 4; j++) {
        float lo[8], hi[8];
        #pragma unroll
        for (int i = 0; i < 8; i++) unpack2(acc[i][j], lo[i], hi[i]);
        float* r0 = buf + (n0 + 2 * j) * 68 + m0;
        float* r1 = r0 + 68;
        *reinterpret_cast<float4*>(r0) =
            make_float4(fmaxf(lo[0],0.f), fmaxf(lo[1],0.f), fmaxf(lo[2],0.f), fmaxf(lo[3],0.f));
        *reinterpret_cast<float4*>(r0 + 4) =
            make_float4(fmaxf(lo[4],0.f), fmaxf(lo[5],0.f), fmaxf(lo[6],0.f), fmaxf(lo[7],0.f));
        *reinterpret_cast<float4*>(r1) =
            make_float4(fmaxf(hi[0],0.f), fmaxf(hi[1],0.f), fmaxf(hi[2],0.f), fmaxf(hi[3],0.f));
        *reinterpret_cast<float4*>(r1 + 4) =
            make_float4(fmaxf(hi[4],0.f), fmaxf(hi[5],0.f), fmaxf(hi[6],0.f), fmaxf(hi[7],0.f));
    }
    __syncthreads();

    // ---- GEMM 2: h2 = relu(h1 @ W3 + b3) ----
    gemm_tile(W3, b3s, buf, wbuf, wbuf_u32, m0, n0, tid, false, acc);

    // ---- logits: h2 . Wf + bf ----
    float pl[8] = {0.f, 0.f, 0.f, 0.f, 0.f, 0.f, 0.f, 0.f};
    #pragma unroll
    for (int j = 0; j < 4; j++) {
        float lo[8], hi[8];
        #pragma unroll
        for (int i = 0; i < 8; i++) unpack2(acc[i][j], lo[i], hi[i]);
        const float wlo = wfs[n0 + 2 * j], whi = wfs[n0 + 2 * j + 1];
        #pragma unroll
        for (int i = 0; i < 8; i++) {
            pl[i] = fmaf(fmaxf(lo[i], 0.f), wlo, pl[i]);
            pl[i] = fmaf(fmaxf(hi[i], 0.f), whi, pl[i]);
        }
    }
    #pragma unroll
    for (int i = 0; i < 8; i++) {
        float v = pl[i];
        v += __shfl_xor_sync(0xffffffffu, v, 1);
        v += __shfl_xor_sync(0xffffffffu, v, 2);
        v += __shfl_xor_sync(0xffffffffu, v, 4);
        pl[i] = v;
    }
    if (ln == 0) {
        #pragma unroll
        for (int i = 0; i < 8; i++) red[(m0 + i) * 4 + warpn] = pl[i];
    }
    __syncthreads();
    if (tid < 64) {
        float s = red[tid * 4] + red[tid * 4 + 1] + red[tid * 4 + 2] + red[tid * 4 + 3]
                  + bfp[0];
        out[lbase + tid] = s;
    }
}

// ---------------- launcher -----------------------------------------------------
extern "C" void kernel_launch(void* const* d_in, const int* in_sizes, int n_in,
                              void* d_out, int out_size)
{
    const float* query = (const float*)d_in[0];
    const float* key   = (const float*)d_in[1];
    const float* Wqe   = (const float*)d_in[2];
    const float* bqe   = (const float*)d_in[3];
    const float* Wke   = (const float*)d_in[4];
    const float* bke   = (const float*)d_in[5];
    const float* W1    = (const float*)d_in[6];
    const float* b1    = (const float*)d_in[7];
    const float* W2    = (const float*)d_in[8];
    const float* b2    = (const float*)d_in[9];
    const float* W3    = (const float*)d_in[10];
    const float* b3    = (const float*)d_in[11];
    const float* Wf    = (const float*)d_in[12];
    const float* bf    = (const float*)d_in[13];
    const float* Wv1   = (const float*)d_in[14];
    const float* bv1   = (const float*)d_in[15];
    const float* Wv2   = (const float*)d_in[16];
    const float* bv2   = (const float*)d_in[17];
    float* out = (float*)d_out;

    void *p_qf, *p_kf, *p_qp, *p_vq, *p_kpT, *p_vkT;
    cudaGetSymbolAddress(&p_qf,  g_qf);
    cudaGetSymbolAddress(&p_kf,  g_kf);
    cudaGetSymbolAddress(&p_qp,  g_qp);
    cudaGetSymbolAddress(&p_vq,  g_vq);
    cudaGetSymbolAddress(&p_kpT, g_kpT);
    cudaGetSymbolAddress(&p_vkT, g_vkT);

    dim3 pgrid(4, 32);   // N/64 x M/32

    // encoders
    proj_kernel<<<pgrid, 256>>>(query, Wqe, bqe, (float*)p_qf, EE, 0, 1, 0, 0);
    proj_kernel<<<pgrid, 256>>>(key,   Wke, bke, (float*)p_kf, EE, 0, 1, 0, 0);
    // pairwise pre-projections
    proj_kernel<<<pgrid, 256>>>((const float*)p_qf, W1,  nullptr, (float*)p_qp,  HH, 0,   0, 0, 0);
    proj_kernel<<<pgrid, 256>>>((const float*)p_kf, W1,  nullptr, (float*)p_kpT, HH, 256, 0, 1, MR);
    proj_kernel<<<pgrid, 256>>>((const float*)p_qf, Wv1, nullptr, (float*)p_vq,  HH, 0,   0, 0, 0);
    proj_kernel<<<pgrid, 256>>>((const float*)p_kf, Wv1, nullptr, (float*)p_vkT, HH, 256, 0, 1, MR);

    // main fused pairwise-MLP kernel
    const int smem_bytes = (256 * 68 + 4096 + 8 * 256) * 4;   // 94208
    cudaFuncSetAttribute(pair_mlp_kernel,
                         cudaFuncAttributeMaxDynamicSharedMemorySize, smem_bytes);
    pair_mlp_kernel<<<BB * SQ * (SKK / 64), 256, smem_bytes>>>(
        W2, b2, W3, b3, Wf, bf, b1, bv1, Wv2, bv2, out);
}

// round 4
// speedup vs baseline: 2.5456x; 2.5456x over previous
#include <cuda_runtime.h>
#include <cuda_bf16.h>
#include <math.h>
#include <stdint.h>

// Problem dims (fixed)
#define BB   2
#define SQ   512
#define SKK  512
#define EE   512
#define HH   256
#define MR   1024            // B*SQ = B*SK
#define NTOT (BB*SQ*SKK)     // 524288

// ---------------- scratch (device globals; no allocation allowed) -------------
__device__ float g_qf [MR*HH];
__device__ float g_kf [MR*HH];
__device__ float g_qp [MR*HH];
__device__ float g_vq [MR*HH];
__device__ float g_kpT[HH*MR];   // [H][B*SK]
__device__ float g_vkT[HH*MR];   // [H][B*SK]
// split bf16 weight images: word layout [layer][k][nw] (nw = n/2, bf16x2)
__device__ __align__(16) uint32_t g_Wh[2 * 256 * 128];
__device__ __align__(16) uint32_t g_Wl[2 * 256 * 128];

// SMEM map (byte offsets from 1024-aligned base)
#define SM_AHI 0u        // 128 rows x 512B  (bf16 hi)
#define SM_ALO 65536u    // 128 rows x 512B  (bf16 lo)
#define SM_B   131072u   // 2 bufs x 32KB (hi 16KB + lo 16KB each)
#define SM_VEC 196608u
#define SMEM_BYTES (206848 + 1024)

// ---------------- PTX helpers --------------------------------------------------
__device__ __forceinline__ uint32_t smem_u32(const void* p) {
    return (uint32_t)__cvta_generic_to_shared(p);
}
__device__ __forceinline__ void ldsm_x4(uint32_t (&r)[4], uint32_t addr) {
    asm volatile("ldmatrix.sync.aligned.m8n8.x4.shared.b16 {%0,%1,%2,%3}, [%4];"
        : "=r"(r[0]), "=r"(r[1]), "=r"(r[2]), "=r"(r[3]) : "r"(addr));
}
__device__ __forceinline__ void ldsm_x4_t(uint32_t (&r)[4], uint32_t addr) {
    asm volatile("ldmatrix.sync.aligned.m8n8.x4.trans.shared.b16 {%0,%1,%2,%3}, [%4];"
        : "=r"(r[0]), "=r"(r[1]), "=r"(r[2]), "=r"(r[3]) : "r"(addr));
}
__device__ __forceinline__ void mma_bf16(float (&d)[4], const uint32_t (&a)[4],
                                         uint32_t b0, uint32_t b1) {
    asm volatile("mma.sync.aligned.m16n8k16.row.col.f32.bf16.bf16.f32 "
        "{%0,%1,%2,%3}, {%4,%5,%6,%7}, {%8,%9}, {%0,%1,%2,%3};"
        : "+f"(d[0]), "+f"(d[1]), "+f"(d[2]), "+f"(d[3])
        : "r"(a[0]), "r"(a[1]), "r"(a[2]), "r"(a[3]), "r"(b0), "r"(b1));
}

// ---------------- small math helpers ------------------------------------------
__device__ __forceinline__ uint32_t bf16x2_of(float v_hi, float v_lo) {
    uint32_t r;
    asm("cvt.rn.bf16x2.f32 %0, %1, %2;" : "=r"(r) : "f"(v_hi), "f"(v_lo));
    return r;
}
// pack (v0 -> low half, v1 -> high half); lw = bf16 residuals
__device__ __forceinline__ void split_pair(float v0, float v1, uint32_t& hw, uint32_t& lw) {
    hw = bf16x2_of(v1, v0);
    float h0 = __uint_as_float(hw << 16);
    float h1 = __uint_as_float(hw & 0xffff0000u);
    lw = bf16x2_of(v1 - h1, v0 - h0);
}
__device__ __forceinline__ float softplusf(float x) {
    if (x > 20.f) return x;
    return log1pf(expf(x));
}

// ---------------- weight split prologue ----------------------------------------
__global__ __launch_bounds__(256)
void wsplit_kernel(const float* __restrict__ W2, const float* __restrict__ W3)
{
    int idx = blockIdx.x * 256 + threadIdx.x;     // 0..65535
    int layer = idx >> 15;
    int rem   = idx & 32767;
    int k  = rem >> 7;          // 0..255
    int nw = rem & 127;         // 0..127
    const float* W = layer ? W3 : W2;
    float v0 = W[k * 256 + nw * 2];
    float v1 = W[k * 256 + nw * 2 + 1];
    uint32_t hw, lw;
    split_pair(v0, v1, hw, lw);
    g_Wh[idx] = hw;
    g_Wl[idx] = lw;
}

// ---------------- prologue: batched 1024x256 projection GEMM ------------------
struct ProjJob {
    const float* A; const float* W; const float* bias; float* C;
    int wrow0; int doRelu; int doTrans;
};

__global__ __launch_bounds__(256)
void proj_batch_kernel(ProjJob j0, ProjJob j1, ProjJob j2, ProjJob j3, int K)
{
    ProjJob jb = (blockIdx.z == 0) ? j0 : (blockIdx.z == 1) ? j1 :
                 (blockIdx.z == 2) ? j2 : j3;
    __shared__ float As[16][36];
    __shared__ float Ws[16][68];
    const int tid = threadIdx.x;
    const int m0  = blockIdx.y * 32;
    const int n0  = blockIdx.x * 64;
    const int ty  = tid >> 4, tx = tid & 15;

    float acc[2][4] = {};
    const int nch = K >> 4;
    for (int ch = 0; ch < nch; ch++) {
        const int kc = ch << 4;
        __syncthreads();
        {
            int e = tid;        int m = e >> 4, kk = e & 15;
            As[kk][m] = jb.A[(m0 + m) * K + kc + kk];
            e = tid + 256;      m = e >> 4;     kk = e & 15;
            As[kk][m] = jb.A[(m0 + m) * K + kc + kk];
        }
        #pragma unroll
        for (int i = 0; i < 4; i++) {
            int e = tid + (i << 8);
            int kk = e >> 6, n = e & 63;
            Ws[kk][n] = jb.W[(jb.wrow0 + kc + kk) * 256 + n0 + n];
        }
        __syncthreads();
        #pragma unroll
        for (int kk = 0; kk < 16; kk++) {
            float a0 = As[kk][ty * 2], a1 = As[kk][ty * 2 + 1];
            float w0 = Ws[kk][tx * 4], w1 = Ws[kk][tx * 4 + 1];
            float w2 = Ws[kk][tx * 4 + 2], w3 = Ws[kk][tx * 4 + 3];
            acc[0][0] = fmaf(a0, w0, acc[0][0]);
            acc[0][1] = fmaf(a0, w1, acc[0][1]);
            acc[0][2] = fmaf(a0, w2, acc[0][2]);
            acc[0][3] = fmaf(a0, w3, acc[0][3]);
            acc[1][0] = fmaf(a1, w0, acc[1][0]);
            acc[1][1] = fmaf(a1, w1, acc[1][1]);
            acc[1][2] = fmaf(a1, w2, acc[1][2]);
            acc[1][3] = fmaf(a1, w3, acc[1][3]);
        }
    }
    #pragma unroll
    for (int i = 0; i < 2; i++) {
        const int r = m0 + ty * 2 + i;
        #pragma unroll
        for (int j = 0; j < 4; j++) {
            const int n = n0 + tx * 4 + j;
            float v = acc[i][j] + (jb.bias ? jb.bias[n] : 0.f);
            if (jb.doRelu) v = fmaxf(v, 0.f);
            if (jb.doTrans) jb.C[n * MR + r] = v;
            else            jb.C[r * 256 + n] = v;
        }
    }
}

// ---------------- main pairwise-MLP kernel (mma.sync split-bf16) ---------------

// copy one 32-row k-chunk (hi+lo, 16KB each) into smem buffer with xor swizzle
__device__ __forceinline__ void cp_chunk(const char* __restrict__ srcH,
                                         const char* __restrict__ srcL,
                                         uint32_t dstbase, int tid)
{
    #pragma unroll
    for (int i = 0; i < 2; i++) {
        int e = tid + i * 512;                 // 0..1023
        int k = e >> 5, u = e & 31;            // row, 16B unit
        uint32_t d = dstbase + (uint32_t)k * 512u + (uint32_t)((u ^ (k & 7)) << 4);
        asm volatile("cp.async.cg.shared.global [%0], [%1], 16;"
                     :: "r"(d), "l"(srcH + e * 16));
        asm volatile("cp.async.cg.shared.global [%0], [%1], 16;"
                     :: "r"(d + 16384u), "l"(srcL + e * 16));
    }
    asm volatile("cp.async.commit_group;" ::: "memory");
}

// One 128x256x256 split-bf16 GEMM: acc += A(smem hi/lo) @ W(layer stream)
__device__ __forceinline__ void gemm_pass(uint32_t abase,
                                          const char* __restrict__ WhL,
                                          const char* __restrict__ WlL,
                                          int warpM, int warpN, int lane, int tid,
                                          float (&acc)[2][8][4])
{
    const int rit  = (lane & 7) | (((lane >> 3) & 1) << 3); // row within 16-tile
    const int koff = lane >> 4;                              // 0/1: unit select
    uint32_t a_row[2]; int a_sw[2];
    #pragma unroll
    for (int mt = 0; mt < 2; mt++) {
        int rr = warpM * 32 + mt * 16 + rit;
        a_row[mt] = abase + (uint32_t)rr * 512u;
        a_sw[mt]  = rr & 7;
    }
    const uint32_t wb = abase + SM_B;

    #pragma unroll 1
    for (int c = 0; c < 8; c++) {
        asm volatile("cp.async.wait_group 0;" ::: "memory");
        __syncthreads();
        if (c < 7)
            cp_chunk(WhL + (c + 1) * 16384, WlL + (c + 1) * 16384,
                     wb + (uint32_t)(((c + 1) & 1) * 32768), tid);
        const uint32_t bbase = wb + (uint32_t)((c & 1) * 32768);
        #pragma unroll
        for (int s = 0; s < 2; s++) {
            const int k16 = c * 2 + s;
            uint32_t ah[2][4], al[2][4];
            #pragma unroll
            for (int mt = 0; mt < 2; mt++) {
                uint32_t unit = (uint32_t)(k16 * 2 + koff);
                uint32_t o = ((unit ^ (uint32_t)a_sw[mt]) << 4);
                ldsm_x4(ah[mt], a_row[mt] + o);
                ldsm_x4(al[mt], a_row[mt] + 65536u + o);
            }
            const int kl = s * 16 + rit;
            const uint32_t brow = bbase + (uint32_t)kl * 512u;
            const uint32_t ksw = (uint32_t)(kl & 7);
            #pragma unroll
            for (int np = 0; np < 4; np++) {
                uint32_t bh[4], bl[4];
                uint32_t nunit = (uint32_t)(warpN * 8 + np * 2 + koff);
                uint32_t o = ((nunit ^ ksw) << 4);
                ldsm_x4_t(bh, brow + o);
                ldsm_x4_t(bl, brow + 16384u + o);
                #pragma unroll
                for (int mt = 0; mt < 2; mt++) {
                    mma_bf16(acc[mt][np * 2],     ah[mt], bh[0], bh[1]);
                    mma_bf16(acc[mt][np * 2],     al[mt], bh[0], bh[1]);
                    mma_bf16(acc[mt][np * 2],     ah[mt], bl[0], bl[1]);
                    mma_bf16(acc[mt][np * 2 + 1], ah[mt], bh[2], bh[3]);
                    mma_bf16(acc[mt][np * 2 + 1], al[mt], bh[2], bh[3]);
                    mma_bf16(acc[mt][np * 2 + 1], ah[mt], bl[2], bl[3]);
                }
            }
        }
    }
}

__global__ __launch_bounds__(512, 1)
void pair_mma_kernel(const float* __restrict__ b1,  const float* __restrict__ b2,
                     const float* __restrict__ b3,  const float* __restrict__ Wf,
                     const float* __restrict__ bfp, const float* __restrict__ bv1,
                     const float* __restrict__ Wv2, const float* __restrict__ bv2,
                     float* __restrict__ out)
{
    extern __shared__ char smraw[];
    const uint32_t smbase = smem_u32(smraw);
    const uint32_t abase  = (smbase + 1023u) & ~1023u;
    char* smp = smraw + (abase - smbase);
    float* qpb  = (float*)(smp + SM_VEC);
    float* vqb  = qpb + 256;
    float* b2s  = vqb + 256;
    float* b3s  = b2s + 256;
    float* wfs  = b3s + 256;
    float* wv2s = wfs + 256;
    float* red  = wv2s + 256;   // 512 floats: [row][warpN]
    float* vred = red + 512;    // 512 floats: [key][p]

    const int tid   = threadIdx.x;
    const int lane  = tid & 31;
    const int w     = tid >> 5;
    const int warpM = w & 3, warpN = w >> 2;
    const int bid = blockIdx.x;
    const int kt  = bid & 3;
    const int q   = (bid >> 2) & 511;
    const int b   = bid >> 11;
    const int k0  = kt << 7;
    const int lbase = (b * SQ + q) * SKK + k0;

    // prefetch W2 chunk0 immediately
    cp_chunk((const char*)g_Wh, (const char*)g_Wl, abase + SM_B, tid);

    // vectors
    {
        const int r = (b * SQ + q) * HH;
        if (tid < 256) {
            qpb[tid] = g_qp[r + tid] + b1[tid];
            b2s[tid] = b2[tid];
            wfs[tid] = Wf[tid];
        } else {
            int u = tid & 255;
            vqb[u]  = g_vq[r + u] + bv1[u];
            b3s[u]  = b3[u];
            wv2s[u] = Wv2[u];
        }
    }
    __syncthreads();

    // ---- A build: h0[m][j] = relu(qp[j]+b1[j] + kpT[j][key]) -> bf16 hi/lo ----
    {
        const int quad = tid >> 7;         // 0..3
        const int m    = tid & 127;
        const int rowb = b * SKK + k0 + m;
        char* arow = smp + (uint32_t)m * 512u;
        #pragma unroll 4
        for (int g = 0; g < 32; g++) {
            int j0 = g * 8 + quad * 2;
            float v0 = fmaxf(qpb[j0]     + g_kpT[j0 * MR + rowb],       0.f);
            float v1 = fmaxf(qpb[j0 + 1] + g_kpT[(j0 + 1) * MR + rowb], 0.f);
            uint32_t hw, lw;
            split_pair(v0, v1, hw, lw);
            uint32_t off = (uint32_t)(((g ^ (m & 7)) << 4) + quad * 4);
            *(uint32_t*)(arow + SM_AHI + off) = hw;
            *(uint32_t*)(arow + SM_ALO + off) = lw;
        }
    }

    // ---- variance partials (overlaps W2 chunk0 copy latency) ----
    {
        const int p = tid >> 7, m = tid & 127;
        const int rowb = b * SKK + k0 + m;
        float va = 0.f;
        #pragma unroll 8
        for (int jj = 0; jj < 64; jj++) {
            int j = p * 64 + jj;
            va = fmaf(fmaxf(vqb[j] + g_vkT[j * MR + rowb], 0.f), wv2s[j], va);
        }
        vred[m * 4 + p] = va;
    }

    // ---- GEMM 1: D = h0 @ W2 ----
    float acc[2][8][4];
    #pragma unroll
    for (int i = 0; i < 2; i++)
        #pragma unroll
        for (int j = 0; j < 8; j++)
            #pragma unroll
            for (int e = 0; e < 4; e++) acc[i][j][e] = 0.f;
    gemm_pass(abase, (const char*)g_Wh, (const char*)g_Wl, warpM, warpN, lane, tid, acc);
    __syncthreads();   // all readers of h0 done; vred complete

    // variance finalize
    if (tid < 128) {
        float s = vred[tid * 4] + vred[tid * 4 + 1] + vred[tid * 4 + 2] + vred[tid * 4 + 3]
                  + bv2[0];
        out[NTOT + lbase + tid] = softplusf(s);
    }

    // prefetch W3 chunk0 (buf0 free: all warps past GEMM1)
    cp_chunk((const char*)g_Wh + 131072, (const char*)g_Wl + 131072, abase + SM_B, tid);

    // ---- epilogue 1: h1 = relu(D + b2) -> A hi/lo buffers ----
    {
        const int g  = lane >> 2;
        const int tg = lane & 3;
        #pragma unroll
        for (int mt = 0; mt < 2; mt++) {
            int r0 = warpM * 32 + mt * 16 + g;
            int r1 = r0 + 8;
            uint32_t row0 = (uint32_t)r0 * 512u;
            uint32_t row1 = (uint32_t)r1 * 512u;
            #pragma unroll
            for (int nt = 0; nt < 8; nt++) {
                int c0 = warpN * 64 + nt * 8 + tg * 2;
                float b20 = b2s[c0], b21 = b2s[c0 + 1];
                float v00 = fmaxf(acc[mt][nt][0] + b20, 0.f);
                float v01 = fmaxf(acc[mt][nt][1] + b21, 0.f);
                float v10 = fmaxf(acc[mt][nt][2] + b20, 0.f);
                float v11 = fmaxf(acc[mt][nt][3] + b21, 0.f);
                uint32_t hw0, lw0, hw1, lw1;
                split_pair(v00, v01, hw0, lw0);
                split_pair(v10, v11, hw1, lw1);
                uint32_t unit = (uint32_t)(c0 >> 3);
                uint32_t o0 = row0 + ((unit ^ (uint32_t)(r0 & 7)) << 4) + (uint32_t)(tg * 4);
                uint32_t o1 = row1 + ((unit ^ (uint32_t)(r1 & 7)) << 4) + (uint32_t)(tg * 4);
                *(uint32_t*)(smp + SM_AHI + o0) = hw0;
                *(uint32_t*)(smp + SM_ALO + o0) = lw0;
                *(uint32_t*)(smp + SM_AHI + o1) = hw1;
                *(uint32_t*)(smp + SM_ALO + o1) = lw1;
            }
        }
    }
    __syncthreads();

    // ---- GEMM 2: D = h1 @ W3 ----
    #pragma unroll
    for (int i = 0; i < 2; i++)
        #pragma unroll
        for (int j = 0; j < 8; j++)
            #pragma unroll
            for (int e = 0; e < 4; e++) acc[i][j][e] = 0.f;
    gemm_pass(abase, (const char*)g_Wh + 131072, (const char*)g_Wl + 131072,
              warpM, warpN, lane, tid, acc);

    // ---- epilogue 2: logit = relu(D + b3) . Wf, cross-warp reduce ----
    {
        const int g  = lane >> 2;
        const int tg = lane & 3;
        #pragma unroll
        for (int mt = 0; mt < 2; mt++) {
            float lg0 = 0.f, lg1 = 0.f;
            #pragma unroll
            for (int nt = 0; nt < 8; nt++) {
                int c0 = warpN * 64 + nt * 8 + tg * 2;
                float b30 = b3s[c0], b31 = b3s[c0 + 1];
                float w0  = wfs[c0], w1  = wfs[c0 + 1];
                lg0 = fmaf(fmaxf(acc[mt][nt][0] + b30, 0.f), w0, lg0);
                lg0 = fmaf(fmaxf(acc[mt][nt][1] + b31, 0.f), w1, lg0);
                lg1 = fmaf(fmaxf(acc[mt][nt][2] + b30, 0.f), w0, lg1);
                lg1 = fmaf(fmaxf(acc[mt][nt][3] + b31, 0.f), w1, lg1);
            }
            lg0 += __shfl_xor_sync(0xffffffffu, lg0, 1);
            lg0 += __shfl_xor_sync(0xffffffffu, lg0, 2);
            lg1 += __shfl_xor_sync(0xffffffffu, lg1, 1);
            lg1 += __shfl_xor_sync(0xffffffffu, lg1, 2);
            if (tg == 0) {
                int r0 = warpM * 32 + mt * 16 + g;
                red[r0 * 4 + warpN]       = lg0;
                red[(r0 + 8) * 4 + warpN] = lg1;
            }
        }
    }
    __syncthreads();
    if (tid < 128) {
        float s = red[tid * 4] + red[tid * 4 + 1] + red[tid * 4 + 2] + red[tid * 4 + 3]
                  + bfp[0];
        out[lbase + tid] = s;
    }
}

// ---------------- launcher -----------------------------------------------------
extern "C" void kernel_launch(void* const* d_in, const int* in_sizes, int n_in,
                              void* d_out, int out_size)
{
    const float* query = (const float*)d_in[0];
    const float* key   = (const float*)d_in[1];
    const float* Wqe   = (const float*)d_in[2];
    const float* bqe   = (const float*)d_in[3];
    const float* Wke   = (const float*)d_in[4];
    const float* bke   = (const float*)d_in[5];
    const float* W1    = (const float*)d_in[6];
    const float* b1    = (const float*)d_in[7];
    const float* W2    = (const float*)d_in[8];
    const float* b2    = (const float*)d_in[9];
    const float* W3    = (const float*)d_in[10];
    const float* b3    = (const float*)d_in[11];
    const float* Wf    = (const float*)d_in[12];
    const float* bf    = (const float*)d_in[13];
    const float* Wv1   = (const float*)d_in[14];
    const float* bv1   = (const float*)d_in[15];
    const float* Wv2   = (const float*)d_in[16];
    const float* bv2   = (const float*)d_in[17];
    float* out = (float*)d_out;

    void *p_qf, *p_kf, *p_qp, *p_vq, *p_kpT, *p_vkT;
    cudaGetSymbolAddress(&p_qf,  g_qf);
    cudaGetSymbolAddress(&p_kf,  g_kf);
    cudaGetSymbolAddress(&p_qp,  g_qp);
    cudaGetSymbolAddress(&p_vq,  g_vq);
    cudaGetSymbolAddress(&p_kpT, g_kpT);
    cudaGetSymbolAddress(&p_vkT, g_vkT);

    // weight split (independent of projections)
    wsplit_kernel<<<256, 256>>>(W2, W3);

    // encoders: qf = relu(query@Wqe+bqe), kf = relu(key@Wke+bke)
    ProjJob e0 { query, Wqe, bqe, (float*)p_qf, 0, 1, 0 };
    ProjJob e1 { key,   Wke, bke, (float*)p_kf, 0, 1, 0 };
    proj_batch_kernel<<<dim3(4, 32, 2), 256>>>(e0, e1, e0, e0, EE);

    // stage-2 projections
    ProjJob s0 { (const float*)p_qf, W1,  nullptr, (float*)p_qp,  0,   0, 0 };
    ProjJob s1 { (const float*)p_kf, W1,  nullptr, (float*)p_kpT, 256, 0, 1 };
    ProjJob s2 { (const float*)p_qf, Wv1, nullptr, (float*)p_vq,  0,   0, 0 };
    ProjJob s3 { (const float*)p_kf, Wv1, nullptr, (float*)p_vkT, 256, 0, 1 };
    proj_batch_kernel<<<dim3(4, 32, 4), 256>>>(s0, s1, s2, s3, HH);

    // main fused pairwise-MLP kernel (mma.sync split-bf16)
    cudaFuncSetAttribute(pair_mma_kernel,
                         cudaFuncAttributeMaxDynamicSharedMemorySize, SMEM_BYTES);
    pair_mma_kernel<<<BB * SQ * (SKK / 128), 512, SMEM_BYTES>>>(
        b1, b2, b3, Wf, bf, bv1, Wv2, bv2, out);
}

// round 5
// speedup vs baseline: 2.6043x; 1.0231x over previous
#include <cuda_runtime.h>
#include <cuda_bf16.h>
#include <math.h>
#include <stdint.h>

// Problem dims (fixed)
#define BB   2
#define SQ   512
#define SKK  512
#define EE   512
#define HH   256
#define MR   1024            // B*SQ = B*SK
#define NTOT (BB*SQ*SKK)     // 524288

// ---------------- scratch (device globals; no allocation allowed) -------------
__device__ float g_qf [MR*HH];
__device__ float g_kf [MR*HH];
__device__ float g_qp [MR*HH];
__device__ float g_vq [MR*HH];
__device__ float g_kpT[HH*MR];   // [H][B*SK]
__device__ float g_vkT[HH*MR];   // [H][B*SK]
// split bf16 weight images: word layout [layer][k][nw] (nw = n/2, bf16x2)
__device__ __align__(16) uint32_t g_Wh[2 * 256 * 128];
__device__ __align__(16) uint32_t g_Wl[2 * 256 * 128];

// SMEM map (byte offsets from 1024-aligned base)
#define SM_AHI 0u        // 128 rows x 512B  (bf16 hi)
#define SM_ALO 65536u    // 128 rows x 512B  (bf16 lo)
#define SM_B   131072u   // 2 bufs x 32KB (hi 16KB + lo 16KB each)
#define SM_VEC 196608u
#define SMEM_BYTES (206848 + 1024)

// ---------------- PTX helpers --------------------------------------------------
__device__ __forceinline__ uint32_t smem_u32(const void* p) {
    return (uint32_t)__cvta_generic_to_shared(p);
}
__device__ __forceinline__ void ldsm_x4(uint32_t (&r)[4], uint32_t addr) {
    asm volatile("ldmatrix.sync.aligned.m8n8.x4.shared.b16 {%0,%1,%2,%3}, [%4];"
        : "=r"(r[0]), "=r"(r[1]), "=r"(r[2]), "=r"(r[3]) : "r"(addr));
}
__device__ __forceinline__ void ldsm_x4_t(uint32_t (&r)[4], uint32_t addr) {
    asm volatile("ldmatrix.sync.aligned.m8n8.x4.trans.shared.b16 {%0,%1,%2,%3}, [%4];"
        : "=r"(r[0]), "=r"(r[1]), "=r"(r[2]), "=r"(r[3]) : "r"(addr));
}
__device__ __forceinline__ void mma_bf16(float (&d)[4], const uint32_t (&a)[4],
                                         uint32_t b0, uint32_t b1) {
    asm volatile("mma.sync.aligned.m16n8k16.row.col.f32.bf16.bf16.f32 "
        "{%0,%1,%2,%3}, {%4,%5,%6,%7}, {%8,%9}, {%0,%1,%2,%3};"
        : "+f"(d[0]), "+f"(d[1]), "+f"(d[2]), "+f"(d[3])
        : "r"(a[0]), "r"(a[1]), "r"(a[2]), "r"(a[3]), "r"(b0), "r"(b1));
}
__device__ __forceinline__ unsigned long long pack_dup(float a) {
    unsigned long long r;
    asm("mov.b64 %0, {%1, %1};" : "=l"(r) : "f"(a));
    return r;
}
__device__ __forceinline__ void unpack2(unsigned long long v, float& lo, float& hi) {
    asm("mov.b64 {%0, %1}, %2;" : "=f"(lo), "=f"(hi) : "l"(v));
}
__device__ __forceinline__ void ffma2(unsigned long long& acc, unsigned long long a,
                                      unsigned long long b) {
    asm("fma.rn.f32x2 %0, %1, %2, %0;" : "+l"(acc) : "l"(a), "l"(b));
}

// ---------------- small math helpers ------------------------------------------
__device__ __forceinline__ uint32_t bf16x2_of(float v_hi, float v_lo) {
    uint32_t r;
    asm("cvt.rn.bf16x2.f32 %0, %1, %2;" : "=r"(r) : "f"(v_hi), "f"(v_lo));
    return r;
}
// pack (v0 -> low half, v1 -> high half); lw = bf16 residuals
__device__ __forceinline__ void split_pair(float v0, float v1, uint32_t& hw, uint32_t& lw) {
    hw = bf16x2_of(v1, v0);
    float h0 = __uint_as_float(hw << 16);
    float h1 = __uint_as_float(hw & 0xffff0000u);
    lw = bf16x2_of(v1 - h1, v0 - h0);
}
__device__ __forceinline__ float softplusf(float x) {
    if (x > 20.f) return x;
    return log1pf(expf(x));
}

// ---------------- weight split prologue ----------------------------------------
__global__ __launch_bounds__(256)
void wsplit_kernel(const float* __restrict__ W2, const float* __restrict__ W3)
{
    int idx = blockIdx.x * 256 + threadIdx.x;     // 0..65535
    int layer = idx >> 15;
    int rem   = idx & 32767;
    int k  = rem >> 7;          // 0..255
    int nw = rem & 127;         // 0..127
    const float* W = layer ? W3 : W2;
    float v0 = W[k * 256 + nw * 2];
    float v1 = W[k * 256 + nw * 2 + 1];
    uint32_t hw, lw;
    split_pair(v0, v1, hw, lw);
    g_Wh[idx] = hw;
    g_Wl[idx] = lw;
}

// ---------------- prologue: batched 1024x256 projection GEMM (f32x2) ----------
struct ProjJob {
    const float* A; const float* W; const float* bias; float* C;
    int wrow0; int doRelu; int doTrans;
};

__global__ __launch_bounds__(256)
void proj_batch_kernel(ProjJob j0, ProjJob j1, ProjJob j2, ProjJob j3, int K)
{
    ProjJob jb = (blockIdx.z == 0) ? j0 : (blockIdx.z == 1) ? j1 :
                 (blockIdx.z == 2) ? j2 : j3;
    __shared__ float As[16][36];
    __shared__ float Ws[16][68];
    const int tid = threadIdx.x;
    const int m0  = blockIdx.y * 32;
    const int n0  = blockIdx.x * 64;
    const int ty  = tid >> 4, tx = tid & 15;

    unsigned long long acc2[2][2] = {{0ull, 0ull}, {0ull, 0ull}};
    const int nch = K >> 4;
    for (int ch = 0; ch < nch; ch++) {
        const int kc = ch << 4;
        __syncthreads();
        {
            int e = tid;        int m = e >> 4, kk = e & 15;
            As[kk][m] = jb.A[(m0 + m) * K + kc + kk];
            e = tid + 256;      m = e >> 4;     kk = e & 15;
            As[kk][m] = jb.A[(m0 + m) * K + kc + kk];
        }
        #pragma unroll
        for (int i = 0; i < 4; i++) {
            int e = tid + (i << 8);
            int kk = e >> 6, n = e & 63;
            Ws[kk][n] = jb.W[(jb.wrow0 + kc + kk) * 256 + n0 + n];
        }
        __syncthreads();
        #pragma unroll
        for (int kk = 0; kk < 16; kk++) {
            unsigned long long a0d = pack_dup(As[kk][ty * 2]);
            unsigned long long a1d = pack_dup(As[kk][ty * 2 + 1]);
            unsigned long long w01 = *(const unsigned long long*)&Ws[kk][tx * 4];
            unsigned long long w23 = *(const unsigned long long*)&Ws[kk][tx * 4 + 2];
            ffma2(acc2[0][0], a0d, w01);
            ffma2(acc2[0][1], a0d, w23);
            ffma2(acc2[1][0], a1d, w01);
            ffma2(acc2[1][1], a1d, w23);
        }
    }
    #pragma unroll
    for (int i = 0; i < 2; i++) {
        float vout[4];
        unpack2(acc2[i][0], vout[0], vout[1]);
        unpack2(acc2[i][1], vout[2], vout[3]);
        const int r = m0 + ty * 2 + i;
        #pragma unroll
        for (int j = 0; j < 4; j++) {
            const int n = n0 + tx * 4 + j;
            float v = vout[j] + (jb.bias ? jb.bias[n] : 0.f);
            if (jb.doRelu) v = fmaxf(v, 0.f);
            if (jb.doTrans) jb.C[n * MR + r] = v;
            else            jb.C[r * 256 + n] = v;
        }
    }
}

// ---------------- main pairwise-MLP kernel (mma.sync split-bf16) ---------------

// copy one 32-row k-chunk (hi+lo, 16KB each) into smem buffer with xor swizzle
__device__ __forceinline__ void cp_chunk(const char* __restrict__ srcH,
                                         const char* __restrict__ srcL,
                                         uint32_t dstbase, int tid)
{
    #pragma unroll
    for (int i = 0; i < 2; i++) {
        int e = tid + i * 512;                 // 0..1023
        int k = e >> 5, u = e & 31;            // row, 16B unit
        uint32_t d = dstbase + (uint32_t)k * 512u + (uint32_t)((u ^ (k & 7)) << 4);
        asm volatile("cp.async.cg.shared.global [%0], [%1], 16;"
                     :: "r"(d), "l"(srcH + e * 16));
        asm volatile("cp.async.cg.shared.global [%0], [%1], 16;"
                     :: "r"(d + 16384u), "l"(srcL + e * 16));
    }
    asm volatile("cp.async.commit_group;" ::: "memory");
}

// build 2 adjacent 16B units (g0, g0+1) of one A row: j0 = 8*g + quad*2
__device__ __forceinline__ void a_store_units(char* smp, int m, int quad, int g0,
                                              float v0, float v1, float v2, float v3)
{
    char* arow = smp + (uint32_t)m * 512u;
    uint32_t hw, lw;
    split_pair(v0, v1, hw, lw);
    uint32_t off0 = (uint32_t)(((g0 ^ (m & 7)) << 4) + quad * 4);
    *(uint32_t*)(arow + SM_AHI + off0) = hw;
    *(uint32_t*)(arow + SM_ALO + off0) = lw;
    split_pair(v2, v3, hw, lw);
    uint32_t off1 = (uint32_t)((((g0 + 1) ^ (m & 7)) << 4) + quad * 4);
    *(uint32_t*)(arow + SM_AHI + off1) = hw;
    *(uint32_t*)(arow + SM_ALO + off1) = lw;
}

// One 128x256x256 split-bf16 GEMM: acc += A(smem hi/lo) @ W(layer stream).
// FIRST: additionally builds A slice c+1 (h0 from g_kpT) and accumulates the
// variance dot-product, both interleaved with the MMA stream.
template<bool FIRST>
__device__ __forceinline__ void gemm_pass(uint32_t abase,
                                          const char* __restrict__ WhL,
                                          const char* __restrict__ WlL,
                                          int warpM, int warpN, int lane, int tid,
                                          float (&acc)[2][8][4],
                                          char* smp, const float* __restrict__ qpb,
                                          const float* __restrict__ vqb,
                                          const float* __restrict__ wv2s,
                                          int rowb, float& vacc)
{
    const int rit  = (lane & 7) | (((lane >> 3) & 1) << 3); // row within 16-tile
    const int koff = lane >> 4;                              // 0/1: unit select
    const int quad = tid >> 7;                               // 0..3 (also p)
    const int m    = tid & 127;
    uint32_t a_row[2]; int a_sw[2];
    #pragma unroll
    for (int mt = 0; mt < 2; mt++) {
        int rr = warpM * 32 + mt * 16 + rit;
        a_row[mt] = abase + (uint32_t)rr * 512u;
        a_sw[mt]  = rr & 7;
    }
    const uint32_t wb = abase + SM_B;

    #pragma unroll 1
    for (int c = 0; c < 8; c++) {
        asm volatile("cp.async.wait_group 0;" ::: "memory");
        __syncthreads();
        if (c < 7)
            cp_chunk(WhL + (c + 1) * 16384, WlL + (c + 1) * 16384,
                     wb + (uint32_t)(((c + 1) & 1) * 32768), tid);
        const uint32_t bbase = wb + (uint32_t)((c & 1) * 32768);
        #pragma unroll
        for (int s = 0; s < 2; s++) {
            // ---- early global loads (latency hidden behind MMAs) ----
            float kp0, kp1, kp2, kp3;
            float vk0, vk1, vk2, vk3;
            int j0 = 0, jv = 0;
            if (FIRST) {
                if (c < 7) {
                    int g0 = 4 * (c + 1) + 2 * s;
                    j0 = 8 * g0 + quad * 2;
                    kp0 = g_kpT[j0 * MR + rowb];
                    kp1 = g_kpT[(j0 + 1) * MR + rowb];
                    kp2 = g_kpT[(j0 + 8) * MR + rowb];
                    kp3 = g_kpT[(j0 + 9) * MR + rowb];
                }
                jv = 32 * c + 8 * quad + 4 * s;
                vk0 = g_vkT[jv * MR + rowb];
                vk1 = g_vkT[(jv + 1) * MR + rowb];
                vk2 = g_vkT[(jv + 2) * MR + rowb];
                vk3 = g_vkT[(jv + 3) * MR + rowb];
            }

            // ---- MMA work for k16 = 2c + s ----
            const int k16 = c * 2 + s;
            uint32_t ah[2][4], al[2][4];
            #pragma unroll
            for (int mt = 0; mt < 2; mt++) {
                uint32_t unit = (uint32_t)(k16 * 2 + koff);
                uint32_t o = ((unit ^ (uint32_t)a_sw[mt]) << 4);
                ldsm_x4(ah[mt], a_row[mt] + o);
                ldsm_x4(al[mt], a_row[mt] + 65536u + o);
            }
            const int kl = s * 16 + rit;
            const uint32_t brow = bbase + (uint32_t)kl * 512u;
            const uint32_t ksw = (uint32_t)(kl & 7);
            #pragma unroll
            for (int np = 0; np < 4; np++) {
                uint32_t bh[4], bl[4];
                uint32_t nunit = (uint32_t)(warpN * 8 + np * 2 + koff);
                uint32_t o = ((nunit ^ ksw) << 4);
                ldsm_x4_t(bh, brow + o);
                ldsm_x4_t(bl, brow + 16384u + o);
                #pragma unroll
                for (int mt = 0; mt < 2; mt++) {
                    mma_bf16(acc[mt][np * 2],     ah[mt], bh[0], bh[1]);
                    mma_bf16(acc[mt][np * 2],     al[mt], bh[0], bh[1]);
                    mma_bf16(acc[mt][np * 2],     ah[mt], bl[0], bl[1]);
                    mma_bf16(acc[mt][np * 2 + 1], ah[mt], bh[2], bh[3]);
                    mma_bf16(acc[mt][np * 2 + 1], al[mt], bh[2], bh[3]);
                    mma_bf16(acc[mt][np * 2 + 1], ah[mt], bl[2], bl[3]);
                }
            }

            // ---- late: A-build stores + variance FMAs ----
            if (FIRST) {
                if (c < 7) {
                    int g0 = 4 * (c + 1) + 2 * s;
                    float v0 = fmaxf(qpb[j0]     + kp0, 0.f);
                    float v1 = fmaxf(qpb[j0 + 1] + kp1, 0.f);
                    float v2 = fmaxf(qpb[j0 + 8] + kp2, 0.f);
                    float v3 = fmaxf(qpb[j0 + 9] + kp3, 0.f);
                    a_store_units(smp, m, quad, g0, v0, v1, v2, v3);
                }
                vacc = fmaf(fmaxf(vqb[jv]     + vk0, 0.f), wv2s[jv],     vacc);
                vacc = fmaf(fmaxf(vqb[jv + 1] + vk1, 0.f), wv2s[jv + 1], vacc);
                vacc = fmaf(fmaxf(vqb[jv + 2] + vk2, 0.f), wv2s[jv + 2], vacc);
                vacc = fmaf(fmaxf(vqb[jv + 3] + vk3, 0.f), wv2s[jv + 3], vacc);
            }
        }
    }
}

__global__ __launch_bounds__(512, 1)
void pair_mma_kernel(const float* __restrict__ b1,  const float* __restrict__ b2,
                     const float* __restrict__ b3,  const float* __restrict__ Wf,
                     const float* __restrict__ bfp, const float* __restrict__ bv1,
                     const float* __restrict__ Wv2, const float* __restrict__ bv2,
                     float* __restrict__ out)
{
    extern __shared__ char smraw[];
    const uint32_t smbase = smem_u32(smraw);
    const uint32_t abase  = (smbase + 1023u) & ~1023u;
    char* smp = smraw + (abase - smbase);
    float* qpb  = (float*)(smp + SM_VEC);
    float* vqb  = qpb + 256;
    float* b2s  = vqb + 256;
    float* b3s  = b2s + 256;
    float* wfs  = b3s + 256;
    float* wv2s = wfs + 256;
    float* red  = wv2s + 256;   // 512 floats: [row][warpN]
    float* vred = red + 512;    // 512 floats: [key][p]

    const int tid   = threadIdx.x;
    const int lane  = tid & 31;
    const int w     = tid >> 5;
    const int warpM = w & 3, warpN = w >> 2;
    const int quad  = tid >> 7;
    const int m     = tid & 127;
    const int bid = blockIdx.x;
    const int kt  = bid & 3;
    const int q   = (bid >> 2) & 511;
    const int b   = bid >> 11;
    const int k0  = kt << 7;
    const int rowb  = b * SKK + k0 + m;
    const int lbase = (b * SQ + q) * SKK + k0;

    // prefetch W2 chunk0 immediately
    cp_chunk((const char*)g_Wh, (const char*)g_Wl, abase + SM_B, tid);

    // vectors
    {
        const int r = (b * SQ + q) * HH;
        if (tid < 256) {
            qpb[tid] = g_qp[r + tid] + b1[tid];
            b2s[tid] = b2[tid];
            wfs[tid] = Wf[tid];
        } else {
            int u = tid & 255;
            vqb[u]  = g_vq[r + u] + bv1[u];
            b3s[u]  = b3[u];
            wv2s[u] = Wv2[u];
        }
    }
    __syncthreads();

    // ---- prebuild A slice 0 only (units g=0..3); slices 1..7 built in-loop ----
    {
        #pragma unroll
        for (int gg = 0; gg < 2; gg++) {
            int g0 = gg * 2;
            int j0 = 8 * g0 + quad * 2;
            float v0 = fmaxf(qpb[j0]     + g_kpT[j0 * MR + rowb],       0.f);
            float v1 = fmaxf(qpb[j0 + 1] + g_kpT[(j0 + 1) * MR + rowb], 0.f);
            float v2 = fmaxf(qpb[j0 + 8] + g_kpT[(j0 + 8) * MR + rowb], 0.f);
            float v3 = fmaxf(qpb[j0 + 9] + g_kpT[(j0 + 9) * MR + rowb], 0.f);
            a_store_units(smp, m, quad, g0, v0, v1, v2, v3);
        }
    }

    // ---- GEMM 1: D = h0 @ W2 (A-build + variance interleaved) ----
    float acc[2][8][4];
    #pragma unroll
    for (int i = 0; i < 2; i++)
        #pragma unroll
        for (int j = 0; j < 8; j++)
            #pragma unroll
            for (int e = 0; e < 4; e++) acc[i][j][e] = 0.f;
    float vacc = 0.f;
    gemm_pass<true>(abase, (const char*)g_Wh, (const char*)g_Wl,
                    warpM, warpN, lane, tid, acc,
                    smp, qpb, vqb, wv2s, rowb, vacc);
    vred[m * 4 + quad] = vacc;
    __syncthreads();   // all readers of h0 done; vred complete

    // variance finalize
    if (tid < 128) {
        float s = vred[tid * 4] + vred[tid * 4 + 1] + vred[tid * 4 + 2] + vred[tid * 4 + 3]
                  + bv2[0];
        out[NTOT + lbase + tid] = softplusf(s);
    }

    // prefetch W3 chunk0 (buf0 free: all warps past GEMM1)
    cp_chunk((const char*)g_Wh + 131072, (const char*)g_Wl + 131072, abase + SM_B, tid);

    // ---- epilogue 1: h1 = relu(D + b2) -> A hi/lo buffers ----
    {
        const int g  = lane >> 2;
        const int tg = lane & 3;
        #pragma unroll
        for (int mt = 0; mt < 2; mt++) {
            int r0 = warpM * 32 + mt * 16 + g;
            int r1 = r0 + 8;
            uint32_t row0 = (uint32_t)r0 * 512u;
            uint32_t row1 = (uint32_t)r1 * 512u;
            #pragma unroll
            for (int nt = 0; nt < 8; nt++) {
                int c0 = warpN * 64 + nt * 8 + tg * 2;
                float b20 = b2s[c0], b21 = b2s[c0 + 1];
                float v00 = fmaxf(acc[mt][nt][0] + b20, 0.f);
                float v01 = fmaxf(acc[mt][nt][1] + b21, 0.f);
                float v10 = fmaxf(acc[mt][nt][2] + b20, 0.f);
                float v11 = fmaxf(acc[mt][nt][3] + b21, 0.f);
                uint32_t hw0, lw0, hw1, lw1;
                split_pair(v00, v01, hw0, lw0);
                split_pair(v10, v11, hw1, lw1);
                uint32_t unit = (uint32_t)(c0 >> 3);
                uint32_t o0 = row0 + ((unit ^ (uint32_t)(r0 & 7)) << 4) + (uint32_t)(tg * 4);
                uint32_t o1 = row1 + ((unit ^ (uint32_t)(r1 & 7)) << 4) + (uint32_t)(tg * 4);
                *(uint32_t*)(smp + SM_AHI + o0) = hw0;
                *(uint32_t*)(smp + SM_ALO + o0) = lw0;
                *(uint32_t*)(smp + SM_AHI + o1) = hw1;
                *(uint32_t*)(smp + SM_ALO + o1) = lw1;
            }
        }
    }
    __syncthreads();

    // ---- GEMM 2: D = h1 @ W3 ----
    #pragma unroll
    for (int i = 0; i < 2; i++)
        #pragma unroll
        for (int j = 0; j < 8; j++)
            #pragma unroll
            for (int e = 0; e < 4; e++) acc[i][j][e] = 0.f;
    gemm_pass<false>(abase, (const char*)g_Wh + 131072, (const char*)g_Wl + 131072,
                     warpM, warpN, lane, tid, acc,
                     smp, qpb, vqb, wv2s, rowb, vacc);

    // ---- epilogue 2: logit = relu(D + b3) . Wf, cross-warp reduce ----
    {
        const int g  = lane >> 2;
        const int tg = lane & 3;
        #pragma unroll
        for (int mt = 0; mt < 2; mt++) {
            float lg0 = 0.f, lg1 = 0.f;
            #pragma unroll
            for (int nt = 0; nt < 8; nt++) {
                int c0 = warpN * 64 + nt * 8 + tg * 2;
                float b30 = b3s[c0], b31 = b3s[c0 + 1];
                float w0  = wfs[c0], w1  = wfs[c0 + 1];
                lg0 = fmaf(fmaxf(acc[mt][nt][0] + b30, 0.f), w0, lg0);
                lg0 = fmaf(fmaxf(acc[mt][nt][1] + b31, 0.f), w1, lg0);
                lg1 = fmaf(fmaxf(acc[mt][nt][2] + b30, 0.f), w0, lg1);
                lg1 = fmaf(fmaxf(acc[mt][nt][3] + b31, 0.f), w1, lg1);
            }
            lg0 += __shfl_xor_sync(0xffffffffu, lg0, 1);
            lg0 += __shfl_xor_sync(0xffffffffu, lg0, 2);
            lg1 += __shfl_xor_sync(0xffffffffu, lg1, 1);
            lg1 += __shfl_xor_sync(0xffffffffu, lg1, 2);
            if (tg == 0) {
                int r0 = warpM * 32 + mt * 16 + g;
                red[r0 * 4 + warpN]       = lg0;
                red[(r0 + 8) * 4 + warpN] = lg1;
            }
        }
    }
    __syncthreads();
    if (tid < 128) {
        float s = red[tid * 4] + red[tid * 4 + 1] + red[tid * 4 + 2] + red[tid * 4 + 3]
                  + bfp[0];
        out[lbase + tid] = s;
    }
}

// ---------------- launcher -----------------------------------------------------
extern "C" void kernel_launch(void* const* d_in, const int* in_sizes, int n_in,
                              void* d_out, int out_size)
{
    const float* query = (const float*)d_in[0];
    const float* key   = (const float*)d_in[1];
    const float* Wqe   = (const float*)d_in[2];
    const float* bqe   = (const float*)d_in[3];
    const float* Wke   = (const float*)d_in[4];
    const float* bke   = (const float*)d_in[5];
    const float* W1    = (const float*)d_in[6];
    const float* b1    = (const float*)d_in[7];
    const float* W2    = (const float*)d_in[8];
    const float* b2    = (const float*)d_in[9];
    const float* W3    = (const float*)d_in[10];
    const float* b3    = (const float*)d_in[11];
    const float* Wf    = (const float*)d_in[12];
    const float* bf    = (const float*)d_in[13];
    const float* Wv1   = (const float*)d_in[14];
    const float* bv1   = (const float*)d_in[15];
    const float* Wv2   = (const float*)d_in[16];
    const float* bv2   = (const float*)d_in[17];
    float* out = (float*)d_out;

    void *p_qf, *p_kf, *p_qp, *p_vq, *p_kpT, *p_vkT;
    cudaGetSymbolAddress(&p_qf,  g_qf);
    cudaGetSymbolAddress(&p_kf,  g_kf);
    cudaGetSymbolAddress(&p_qp,  g_qp);
    cudaGetSymbolAddress(&p_vq,  g_vq);
    cudaGetSymbolAddress(&p_kpT, g_kpT);
    cudaGetSymbolAddress(&p_vkT, g_vkT);

    // weight split (independent of projections)
    wsplit_kernel<<<256, 256>>>(W2, W3);

    // encoders: qf = relu(query@Wqe+bqe), kf = relu(key@Wke+bke)
    ProjJob e0 { query, Wqe, bqe, (float*)p_qf, 0, 1, 0 };
    ProjJob e1 { key,   Wke, bke, (float*)p_kf, 0, 1, 0 };
    proj_batch_kernel<<<dim3(4, 32, 2), 256>>>(e0, e1, e0, e0, EE);

    // stage-2 projections
    ProjJob s0 { (const float*)p_qf, W1,  nullptr, (float*)p_qp,  0,   0, 0 };
    ProjJob s1 { (const float*)p_kf, W1,  nullptr, (float*)p_kpT, 256, 0, 1 };
    ProjJob s2 { (const float*)p_qf, Wv1, nullptr, (float*)p_vq,  0,   0, 0 };
    ProjJob s3 { (const float*)p_kf, Wv1, nullptr, (float*)p_vkT, 256, 0, 1 };
    proj_batch_kernel<<<dim3(4, 32, 4), 256>>>(s0, s1, s2, s3, HH);

    // main fused pairwise-MLP kernel (mma.sync split-bf16)
    cudaFuncSetAttribute(pair_mma_kernel,
                         cudaFuncAttributeMaxDynamicSharedMemorySize, SMEM_BYTES);
    pair_mma_kernel<<<BB * SQ * (SKK / 128), 512, SMEM_BYTES>>>(
        b1, b2, b3, Wf, bf, bv1, Wv2, bv2, out);
}

// round 6
// speedup vs baseline: 3.4328x; 1.3181x over previous
#include <cuda_runtime.h>
#include <cuda_bf16.h>
#include <cuda_fp16.h>
#include <math.h>
#include <stdint.h>

// Problem dims (fixed)
#define BB   2
#define SQ   512
#define SKK  512
#define EE   512
#define HH   256
#define MR   1024            // B*SQ = B*SK
#define NTOT (BB*SQ*SKK)     // 524288

// ---------------- scratch (device globals; no allocation allowed) -------------
__device__ float g_qf [MR*HH];
__device__ float g_kf [MR*HH];
__device__ float g_qp [MR*HH];
__device__ float g_vq [MR*HH];
__device__ float g_kpT[HH*MR];   // [H][B*SK]
__device__ float g_vkT[HH*MR];   // [H][B*SK]
// split fp16 weight images: word layout [layer][k][nw] (nw = n/2, f16x2)
__device__ __align__(16) uint32_t g_Wh[2 * 256 * 128];
__device__ __align__(16) uint32_t g_Wl[2 * 256 * 128];

// SMEM map (byte offsets from 1024-aligned base)
#define SM_AHI 0u        // 128 rows x 512B  (fp16 A)
#define SM_B   65536u    // 4 bufs x 32KB (hi 16KB + lo 16KB each)
#define SM_VEC 196608u
#define SMEM_BYTES (206848 + 1024)

// ---------------- PTX helpers --------------------------------------------------
__device__ __forceinline__ uint32_t smem_u32(const void* p) {
    return (uint32_t)__cvta_generic_to_shared(p);
}
__device__ __forceinline__ void ldsm_x4(uint32_t (&r)[4], uint32_t addr) {
    asm volatile("ldmatrix.sync.aligned.m8n8.x4.shared.b16 {%0,%1,%2,%3}, [%4];"
        : "=r"(r[0]), "=r"(r[1]), "=r"(r[2]), "=r"(r[3]) : "r"(addr));
}
__device__ __forceinline__ void ldsm_x4_t(uint32_t (&r)[4], uint32_t addr) {
    asm volatile("ldmatrix.sync.aligned.m8n8.x4.trans.shared.b16 {%0,%1,%2,%3}, [%4];"
        : "=r"(r[0]), "=r"(r[1]), "=r"(r[2]), "=r"(r[3]) : "r"(addr));
}
__device__ __forceinline__ void mma_f16(float (&d)[4], const uint32_t (&a)[4],
                                        uint32_t b0, uint32_t b1) {
    asm volatile("mma.sync.aligned.m16n8k16.row.col.f32.f16.f16.f32 "
        "{%0,%1,%2,%3}, {%4,%5,%6,%7}, {%8,%9}, {%0,%1,%2,%3};"
        : "+f"(d[0]), "+f"(d[1]), "+f"(d[2]), "+f"(d[3])
        : "r"(a[0]), "r"(a[1]), "r"(a[2]), "r"(a[3]), "r"(b0), "r"(b1));
}
__device__ __forceinline__ unsigned long long pack_dup(float a) {
    unsigned long long r;
    asm("mov.b64 %0, {%1, %1};" : "=l"(r) : "f"(a));
    return r;
}
__device__ __forceinline__ void unpack2(unsigned long long v, float& lo, float& hi) {
    asm("mov.b64 {%0, %1}, %2;" : "=f"(lo), "=f"(hi) : "l"(v));
}
__device__ __forceinline__ void ffma2(unsigned long long& acc, unsigned long long a,
                                      unsigned long long b) {
    asm("fma.rn.f32x2 %0, %1, %2, %0;" : "+l"(acc) : "l"(a), "l"(b));
}

// ---------------- small math helpers ------------------------------------------
// pack two floats as f16x2 (v0 -> low half, v1 -> high half)
__device__ __forceinline__ uint32_t f16x2bits(float v0, float v1) {
    __half2 h = __floats2half2_rn(v0, v1);
    return *reinterpret_cast<uint32_t*>(&h);
}
__device__ __forceinline__ float softplusf(float x) {
    if (x > 20.f) return x;
    return log1pf(expf(x));
}

// ---------------- weight split prologue (fp16 hi + fp16 residual) -------------
__global__ __launch_bounds__(256)
void wsplit_kernel(const float* __restrict__ W2, const float* __restrict__ W3)
{
    int idx = blockIdx.x * 256 + threadIdx.x;     // 0..65535
    int layer = idx >> 15;
    int rem   = idx & 32767;
    int k  = rem >> 7;          // 0..255
    int nw = rem & 127;         // 0..127
    const float* W = layer ? W3 : W2;
    float v0 = W[k * 256 + nw * 2];
    float v1 = W[k * 256 + nw * 2 + 1];
    __half2 h = __floats2half2_rn(v0, v1);
    float2 f  = __half22float2(h);
    __half2 l = __floats2half2_rn(v0 - f.x, v1 - f.y);
    g_Wh[idx] = *reinterpret_cast<uint32_t*>(&h);
    g_Wl[idx] = *reinterpret_cast<uint32_t*>(&l);
}

// ---------------- prologue: batched 1024x256 projection GEMM (f32x2) ----------
struct ProjJob {
    const float* A; const float* W; const float* bias; float* C;
    int wrow0; int doRelu; int doTrans;
};

__global__ __launch_bounds__(256)
void proj_batch_kernel(ProjJob j0, ProjJob j1, ProjJob j2, ProjJob j3, int K)
{
    ProjJob jb = (blockIdx.z == 0) ? j0 : (blockIdx.z == 1) ? j1 :
                 (blockIdx.z == 2) ? j2 : j3;
    __shared__ float As[16][36];
    __shared__ float Ws[16][68];
    const int tid = threadIdx.x;
    const int m0  = blockIdx.y * 32;
    const int n0  = blockIdx.x * 64;
    const int ty  = tid >> 4, tx = tid & 15;

    unsigned long long acc2[2][2] = {{0ull, 0ull}, {0ull, 0ull}};
    const int nch = K >> 4;
    for (int ch = 0; ch < nch; ch++) {
        const int kc = ch << 4;
        __syncthreads();
        {
            int e = tid;        int m = e >> 4, kk = e & 15;
            As[kk][m] = jb.A[(m0 + m) * K + kc + kk];
            e = tid + 256;      m = e >> 4;     kk = e & 15;
            As[kk][m] = jb.A[(m0 + m) * K + kc + kk];
        }
        #pragma unroll
        for (int i = 0; i < 4; i++) {
            int e = tid + (i << 8);
            int kk = e >> 6, n = e & 63;
            Ws[kk][n] = jb.W[(jb.wrow0 + kc + kk) * 256 + n0 + n];
        }
        __syncthreads();
        #pragma unroll
        for (int kk = 0; kk < 16; kk++) {
            unsigned long long a0d = pack_dup(As[kk][ty * 2]);
            unsigned long long a1d = pack_dup(As[kk][ty * 2 + 1]);
            unsigned long long w01 = *(const unsigned long long*)&Ws[kk][tx * 4];
            unsigned long long w23 = *(const unsigned long long*)&Ws[kk][tx * 4 + 2];
            ffma2(acc2[0][0], a0d, w01);
            ffma2(acc2[0][1], a0d, w23);
            ffma2(acc2[1][0], a1d, w01);
            ffma2(acc2[1][1], a1d, w23);
        }
    }
    #pragma unroll
    for (int i = 0; i < 2; i++) {
        float vout[4];
        unpack2(acc2[i][0], vout[0], vout[1]);
        unpack2(acc2[i][1], vout[2], vout[3]);
        const int r = m0 + ty * 2 + i;
        #pragma unroll
        for (int j = 0; j < 4; j++) {
            const int n = n0 + tx * 4 + j;
            float v = vout[j] + (jb.bias ? jb.bias[n] : 0.f);
            if (jb.doRelu) v = fmaxf(v, 0.f);
            if (jb.doTrans) jb.C[n * MR + r] = v;
            else            jb.C[r * 256 + n] = v;
        }
    }
}

// ---------------- main pairwise-MLP kernel (mma.sync fp16 2-term) --------------

// copy one 32-row k-chunk (hi+lo, 16KB each) into one of 4 smem buffers
__device__ __forceinline__ void cp_chunk(const char* __restrict__ srcH,
                                         const char* __restrict__ srcL,
                                         uint32_t dstbase, int tid)
{
    #pragma unroll
    for (int i = 0; i < 2; i++) {
        int e = tid + i * 512;                 // 0..1023
        int k = e >> 5, u = e & 31;            // row, 16B unit
        uint32_t d = dstbase + (uint32_t)k * 512u + (uint32_t)((u ^ (k & 7)) << 4);
        asm volatile("cp.async.cg.shared.global [%0], [%1], 16;"
                     :: "r"(d), "l"(srcH + e * 16));
        asm volatile("cp.async.cg.shared.global [%0], [%1], 16;"
                     :: "r"(d + 16384u), "l"(srcL + e * 16));
    }
    asm volatile("cp.async.commit_group;" ::: "memory");
}

// build 2 adjacent 16B units (g0, g0+1) of one A row: j0 = 8*g + quad*2
__device__ __forceinline__ void a_store_units(char* smp, int m, int quad, int g0,
                                              float v0, float v1, float v2, float v3)
{
    char* arow = smp + (uint32_t)m * 512u;
    uint32_t off0 = (uint32_t)(((g0 ^ (m & 7)) << 4) + quad * 4);
    *(uint32_t*)(arow + SM_AHI + off0) = f16x2bits(v0, v1);
    uint32_t off1 = (uint32_t)((((g0 + 1) ^ (m & 7)) << 4) + quad * 4);
    *(uint32_t*)(arow + SM_AHI + off1) = f16x2bits(v2, v3);
}

// One 128x256x256 fp16 2-term GEMM: acc += A(fp16) @ (Bh + Bl).
// 4-stage cp.async pipeline: chunks 0,1,2 must be issued by the caller.
// FIRST: additionally builds A slice c+1 and accumulates the variance dot.
template<bool FIRST>
__device__ __forceinline__ void gemm_pass(uint32_t abase,
                                          const char* __restrict__ WhL,
                                          const char* __restrict__ WlL,
                                          int warpM, int warpN, int lane, int tid,
                                          float (&acc)[2][8][4],
                                          char* smp, const float* __restrict__ qpb,
                                          const float* __restrict__ vqb,
                                          const float* __restrict__ wv2s,
                                          int rowb, float& vacc)
{
    const int rit  = (lane & 7) | (((lane >> 3) & 1) << 3); // row within 16-tile
    const int koff = lane >> 4;                              // 0/1: unit select
    const int quad = tid >> 7;                               // 0..3 (also p)
    const int m    = tid & 127;
    uint32_t a_row[2]; int a_sw[2];
    #pragma unroll
    for (int mt = 0; mt < 2; mt++) {
        int rr = warpM * 32 + mt * 16 + rit;
        a_row[mt] = abase + (uint32_t)rr * 512u;
        a_sw[mt]  = rr & 7;
    }
    const uint32_t wb = abase + SM_B;

    #pragma unroll 1
    for (int c = 0; c < 8; c++) {
        asm volatile("cp.async.wait_group 2;" ::: "memory");
        __syncthreads();
        if (c < 5)
            cp_chunk(WhL + (c + 3) * 16384, WlL + (c + 3) * 16384,
                     wb + (uint32_t)(((c + 3) & 3) * 32768), tid);
        const uint32_t bbase = wb + (uint32_t)((c & 3) * 32768);
        #pragma unroll
        for (int s = 0; s < 2; s++) {
            // ---- early global loads (latency hidden behind MMAs) ----
            float kp0, kp1, kp2, kp3;
            float vk0, vk1, vk2, vk3;
            int j0 = 0, jv = 0;
            if (FIRST) {
                if (c < 7) {
                    int g0 = 4 * (c + 1) + 2 * s;
                    j0 = 8 * g0 + quad * 2;
                    kp0 = g_kpT[j0 * MR + rowb];
                    kp1 = g_kpT[(j0 + 1) * MR + rowb];
                    kp2 = g_kpT[(j0 + 8) * MR + rowb];
                    kp3 = g_kpT[(j0 + 9) * MR + rowb];
                }
                jv = 32 * c + 8 * quad + 4 * s;
                vk0 = g_vkT[jv * MR + rowb];
                vk1 = g_vkT[(jv + 1) * MR + rowb];
                vk2 = g_vkT[(jv + 2) * MR + rowb];
                vk3 = g_vkT[(jv + 3) * MR + rowb];
            }

            // ---- MMA work for k16 = 2c + s ----
            const int k16 = c * 2 + s;
            uint32_t ah[2][4];
            #pragma unroll
            for (int mt = 0; mt < 2; mt++) {
                uint32_t unit = (uint32_t)(k16 * 2 + koff);
                uint32_t o = ((unit ^ (uint32_t)a_sw[mt]) << 4);
                ldsm_x4(ah[mt], a_row[mt] + o);
            }
            const int kl = s * 16 + rit;
            const uint32_t brow = bbase + (uint32_t)kl * 512u;
            const uint32_t ksw = (uint32_t)(kl & 7);
            #pragma unroll
            for (int np = 0; np < 4; np++) {
                uint32_t bh[4], bl[4];
                uint32_t nunit = (uint32_t)(warpN * 8 + np * 2 + koff);
                uint32_t o = ((nunit ^ ksw) << 4);
                ldsm_x4_t(bh, brow + o);
                ldsm_x4_t(bl, brow + 16384u + o);
                #pragma unroll
                for (int mt = 0; mt < 2; mt++) {
                    mma_f16(acc[mt][np * 2],     ah[mt], bh[0], bh[1]);
                    mma_f16(acc[mt][np * 2],     ah[mt], bl[0], bl[1]);
                    mma_f16(acc[mt][np * 2 + 1], ah[mt], bh[2], bh[3]);
                    mma_f16(acc[mt][np * 2 + 1], ah[mt], bl[2], bl[3]);
                }
            }

            // ---- late: A-build stores + variance FMAs ----
            if (FIRST) {
                if (c < 7) {
                    int g0 = 4 * (c + 1) + 2 * s;
                    float v0 = fmaxf(qpb[j0]     + kp0, 0.f);
                    float v1 = fmaxf(qpb[j0 + 1] + kp1, 0.f);
                    float v2 = fmaxf(qpb[j0 + 8] + kp2, 0.f);
                    float v3 = fmaxf(qpb[j0 + 9] + kp3, 0.f);
                    a_store_units(smp, m, quad, g0, v0, v1, v2, v3);
                }
                vacc = fmaf(fmaxf(vqb[jv]     + vk0, 0.f), wv2s[jv],     vacc);
                vacc = fmaf(fmaxf(vqb[jv + 1] + vk1, 0.f), wv2s[jv + 1], vacc);
                vacc = fmaf(fmaxf(vqb[jv + 2] + vk2, 0.f), wv2s[jv + 2], vacc);
                vacc = fmaf(fmaxf(vqb[jv + 3] + vk3, 0.f), wv2s[jv + 3], vacc);
            }
        }
    }
}

__global__ __launch_bounds__(512, 1)
void pair_mma_kernel(const float* __restrict__ b1,  const float* __restrict__ b2,
                     const float* __restrict__ b3,  const float* __restrict__ Wf,
                     const float* __restrict__ bfp, const float* __restrict__ bv1,
                     const float* __restrict__ Wv2, const float* __restrict__ bv2,
                     float* __restrict__ out)
{
    extern __shared__ char smraw[];
    const uint32_t smbase = smem_u32(smraw);
    const uint32_t abase  = (smbase + 1023u) & ~1023u;
    char* smp = smraw + (abase - smbase);
    float* qpb  = (float*)(smp + SM_VEC);
    float* vqb  = qpb + 256;
    float* b2s  = vqb + 256;
    float* b3s  = b2s + 256;
    float* wfs  = b3s + 256;
    float* wv2s = wfs + 256;
    float* red  = wv2s + 256;   // 512 floats: [row][warpN]
    float* vred = red + 512;    // 512 floats: [key][p]

    const int tid   = threadIdx.x;
    const int lane  = tid & 31;
    const int w     = tid >> 5;
    const int warpM = w & 3, warpN = w >> 2;
    const int quad  = tid >> 7;
    const int m     = tid & 127;
    const int bid = blockIdx.x;
    const int kt  = bid & 3;
    const int q   = (bid >> 2) & 511;
    const int b   = bid >> 11;
    const int k0  = kt << 7;
    const int rowb  = b * SKK + k0 + m;
    const int lbase = (b * SQ + q) * SKK + k0;

    // prefetch W2 chunks 0..2 immediately (4-stage pipeline prologue)
    cp_chunk((const char*)g_Wh,         (const char*)g_Wl,         abase + SM_B,          tid);
    cp_chunk((const char*)g_Wh + 16384, (const char*)g_Wl + 16384, abase + SM_B + 32768u, tid);
    cp_chunk((const char*)g_Wh + 32768, (const char*)g_Wl + 32768, abase + SM_B + 65536u, tid);

    // vectors
    {
        const int r = (b * SQ + q) * HH;
        if (tid < 256) {
            qpb[tid] = g_qp[r + tid] + b1[tid];
            b2s[tid] = b2[tid];
            wfs[tid] = Wf[tid];
        } else {
            int u = tid & 255;
            vqb[u]  = g_vq[r + u] + bv1[u];
            b3s[u]  = b3[u];
            wv2s[u] = Wv2[u];
        }
    }
    __syncthreads();

    // ---- prebuild A slice 0 only (units g=0..3); slices 1..7 built in-loop ----
    {
        #pragma unroll
        for (int gg = 0; gg < 2; gg++) {
            int g0 = gg * 2;
            int j0 = 8 * g0 + quad * 2;
            float v0 = fmaxf(qpb[j0]     + g_kpT[j0 * MR + rowb],       0.f);
            float v1 = fmaxf(qpb[j0 + 1] + g_kpT[(j0 + 1) * MR + rowb], 0.f);
            float v2 = fmaxf(qpb[j0 + 8] + g_kpT[(j0 + 8) * MR + rowb], 0.f);
            float v3 = fmaxf(qpb[j0 + 9] + g_kpT[(j0 + 9) * MR + rowb], 0.f);
            a_store_units(smp, m, quad, g0, v0, v1, v2, v3);
        }
    }

    // ---- GEMM 1: D = h0 @ W2 (A-build + variance interleaved) ----
    float acc[2][8][4];
    #pragma unroll
    for (int i = 0; i < 2; i++)
        #pragma unroll
        for (int j = 0; j < 8; j++)
            #pragma unroll
            for (int e = 0; e < 4; e++) acc[i][j][e] = 0.f;
    float vacc = 0.f;
    gemm_pass<true>(abase, (const char*)g_Wh, (const char*)g_Wl,
                    warpM, warpN, lane, tid, acc,
                    smp, qpb, vqb, wv2s, rowb, vacc);
    vred[m * 4 + quad] = vacc;
    __syncthreads();   // all readers of h0 done; vred complete; B bufs free

    // prefetch W3 chunks 0..2 (overlaps epilogue 1)
    cp_chunk((const char*)g_Wh + 131072,         (const char*)g_Wl + 131072,         abase + SM_B,          tid);
    cp_chunk((const char*)g_Wh + 131072 + 16384, (const char*)g_Wl + 131072 + 16384, abase + SM_B + 32768u, tid);
    cp_chunk((const char*)g_Wh + 131072 + 32768, (const char*)g_Wl + 131072 + 32768, abase + SM_B + 65536u, tid);

    // variance finalize
    if (tid < 128) {
        float s = vred[tid * 4] + vred[tid * 4 + 1] + vred[tid * 4 + 2] + vred[tid * 4 + 3]
                  + bv2[0];
        out[NTOT + lbase + tid] = softplusf(s);
    }

    // ---- epilogue 1: h1 = relu(D + b2) -> A buffer (fp16) ----
    {
        const int g  = lane >> 2;
        const int tg = lane & 3;
        #pragma unroll
        for (int mt = 0; mt < 2; mt++) {
            int r0 = warpM * 32 + mt * 16 + g;
            int r1 = r0 + 8;
            uint32_t row0 = (uint32_t)r0 * 512u;
            uint32_t row1 = (uint32_t)r1 * 512u;
            #pragma unroll
            for (int nt = 0; nt < 8; nt++) {
                int c0 = warpN * 64 + nt * 8 + tg * 2;
                float b20 = b2s[c0], b21 = b2s[c0 + 1];
                float v00 = fmaxf(acc[mt][nt][0] + b20, 0.f);
                float v01 = fmaxf(acc[mt][nt][1] + b21, 0.f);
                float v10 = fmaxf(acc[mt][nt][2] + b20, 0.f);
                float v11 = fmaxf(acc[mt][nt][3] + b21, 0.f);
                uint32_t unit = (uint32_t)(c0 >> 3);
                uint32_t o0 = row0 + ((unit ^ (uint32_t)(r0 & 7)) << 4) + (uint32_t)(tg * 4);
                uint32_t o1 = row1 + ((unit ^ (uint32_t)(r1 & 7)) << 4) + (uint32_t)(tg * 4);
                *(uint32_t*)(smp + SM_AHI + o0) = f16x2bits(v00, v01);
                *(uint32_t*)(smp + SM_AHI + o1) = f16x2bits(v10, v11);
            }
        }
    }
    __syncthreads();

    // ---- GEMM 2: D = h1 @ W3 ----
    #pragma unroll
    for (int i = 0; i < 2; i++)
        #pragma unroll
        for (int j = 0; j < 8; j++)
            #pragma unroll
            for (int e = 0; e < 4; e++) acc[i][j][e] = 0.f;
    gemm_pass<false>(abase, (const char*)g_Wh + 131072, (const char*)g_Wl + 131072,
                     warpM, warpN, lane, tid, acc,
                     smp, qpb, vqb, wv2s, rowb, vacc);

    // ---- epilogue 2: logit = relu(D + b3) . Wf, cross-warp reduce ----
    {
        const int g  = lane >> 2;
        const int tg = lane & 3;
        #pragma unroll
        for (int mt = 0; mt < 2; mt++) {
            float lg0 = 0.f, lg1 = 0.f;
            #pragma unroll
            for (int nt = 0; nt < 8; nt++) {
                int c0 = warpN * 64 + nt * 8 + tg * 2;
                float b30 = b3s[c0], b31 = b3s[c0 + 1];
                float w0  = wfs[c0], w1  = wfs[c0 + 1];
                lg0 = fmaf(fmaxf(acc[mt][nt][0] + b30, 0.f), w0, lg0);
                lg0 = fmaf(fmaxf(acc[mt][nt][1] + b31, 0.f), w1, lg0);
                lg1 = fmaf(fmaxf(acc[mt][nt][2] + b30, 0.f), w0, lg1);
                lg1 = fmaf(fmaxf(acc[mt][nt][3] + b31, 0.f), w1, lg1);
            }
            lg0 += __shfl_xor_sync(0xffffffffu, lg0, 1);
            lg0 += __shfl_xor_sync(0xffffffffu, lg0, 2);
            lg1 += __shfl_xor_sync(0xffffffffu, lg1, 1);
            lg1 += __shfl_xor_sync(0xffffffffu, lg1, 2);
            if (tg == 0) {
                int r0 = warpM * 32 + mt * 16 + g;
                red[r0 * 4 + warpN]       = lg0;
                red[(r0 + 8) * 4 + warpN] = lg1;
            }
        }
    }
    __syncthreads();
    if (tid < 128) {
        float s = red[tid * 4] + red[tid * 4 + 1] + red[tid * 4 + 2] + red[tid * 4 + 3]
                  + bfp[0];
        out[lbase + tid] = s;
    }
}

// ---------------- launcher -----------------------------------------------------
extern "C" void kernel_launch(void* const* d_in, const int* in_sizes, int n_in,
                              void* d_out, int out_size)
{
    const float* query = (const float*)d_in[0];
    const float* key   = (const float*)d_in[1];
    const float* Wqe   = (const float*)d_in[2];
    const float* bqe   = (const float*)d_in[3];
    const float* Wke   = (const float*)d_in[4];
    const float* bke   = (const float*)d_in[5];
    const float* W1    = (const float*)d_in[6];
    const float* b1    = (const float*)d_in[7];
    const float* W2    = (const float*)d_in[8];
    const float* b2    = (const float*)d_in[9];
    const float* W3    = (const float*)d_in[10];
    const float* b3    = (const float*)d_in[11];
    const float* Wf    = (const float*)d_in[12];
    const float* bf    = (const float*)d_in[13];
    const float* Wv1   = (const float*)d_in[14];
    const float* bv1   = (const float*)d_in[15];
    const float* Wv2   = (const float*)d_in[16];
    const float* bv2   = (const float*)d_in[17];
    float* out = (float*)d_out;

    void *p_qf, *p_kf, *p_qp, *p_vq, *p_kpT, *p_vkT;
    cudaGetSymbolAddress(&p_qf,  g_qf);
    cudaGetSymbolAddress(&p_kf,  g_kf);
    cudaGetSymbolAddress(&p_qp,  g_qp);
    cudaGetSymbolAddress(&p_vq,  g_vq);
    cudaGetSymbolAddress(&p_kpT, g_kpT);
    cudaGetSymbolAddress(&p_vkT, g_vkT);

    // weight split (independent of projections)
    wsplit_kernel<<<256, 256>>>(W2, W3);

    // encoders: qf = relu(query@Wqe+bqe), kf = relu(key@Wke+bke)
    ProjJob e0 { query, Wqe, bqe, (float*)p_qf, 0, 1, 0 };
    ProjJob e1 { key,   Wke, bke, (float*)p_kf, 0, 1, 0 };
    proj_batch_kernel<<<dim3(4, 32, 2), 256>>>(e0, e1, e0, e0, EE);

    // stage-2 projections
    ProjJob s0 { (const float*)p_qf, W1,  nullptr, (float*)p_qp,  0,   0, 0 };
    ProjJob s1 { (const float*)p_kf, W1,  nullptr, (float*)p_kpT, 256, 0, 1 };
    ProjJob s2 { (const float*)p_qf, Wv1, nullptr, (float*)p_vq,  0,   0, 0 };
    ProjJob s3 { (const float*)p_kf, Wv1, nullptr, (float*)p_vkT, 256, 0, 1 };
    proj_batch_kernel<<<dim3(4, 32, 4), 256>>>(s0, s1, s2, s3, HH);

    // main fused pairwise-MLP kernel (mma.sync fp16 2-term)
    cudaFuncSetAttribute(pair_mma_kernel,
                         cudaFuncAttributeMaxDynamicSharedMemorySize, SMEM_BYTES);
    pair_mma_kernel<<<BB * SQ * (SKK / 128), 512, SMEM_BYTES>>>(
        b1, b2, b3, Wf, bf, bv1, Wv2, bv2, out);
}

// round 7
// speedup vs baseline: 5.0719x; 1.4775x over previous
#include <cuda_runtime.h>
#include <cuda_bf16.h>
#include <cuda_fp16.h>
#include <math.h>
#include <stdint.h>

// Problem dims (fixed)
#define BB   2
#define SQ   512
#define SKK  512
#define EE   512
#define HH   256
#define MR   1024            // B*SQ = B*SK
#define NTOT (BB*SQ*SKK)     // 524288

// ---------------- scratch (device globals; no allocation allowed) -------------
__device__ float g_qf [MR*HH];
__device__ float g_kf [MR*HH];
__device__ float g_qp [MR*HH];
__device__ float g_vq [MR*HH];
__device__ float g_kpT[HH*MR];   // [H][B*SK]
__device__ float g_vkT[HH*MR];   // [H][B*SK]
// fp16 weight images: word layout [layer][k][nw] (nw = n/2, f16x2)
__device__ __align__(16) uint32_t g_Wh[2 * 256 * 128];

// SMEM map (byte offsets from 1024-aligned base)
#define SM_AHI 0u        // 128 rows x 512B  (fp16 A)
#define SM_B   65536u    // 4 bufs x 16KB
#define SM_VEC 131072u
#define SMEM_BYTES (141312 + 1024)

// ---------------- PTX helpers --------------------------------------------------
__device__ __forceinline__ uint32_t smem_u32(const void* p) {
    return (uint32_t)__cvta_generic_to_shared(p);
}
__device__ __forceinline__ void ldsm_x4(uint32_t (&r)[4], uint32_t addr) {
    asm volatile("ldmatrix.sync.aligned.m8n8.x4.shared.b16 {%0,%1,%2,%3}, [%4];"
        : "=r"(r[0]), "=r"(r[1]), "=r"(r[2]), "=r"(r[3]) : "r"(addr));
}
__device__ __forceinline__ void ldsm_x4_t(uint32_t (&r)[4], uint32_t addr) {
    asm volatile("ldmatrix.sync.aligned.m8n8.x4.trans.shared.b16 {%0,%1,%2,%3}, [%4];"
        : "=r"(r[0]), "=r"(r[1]), "=r"(r[2]), "=r"(r[3]) : "r"(addr));
}
__device__ __forceinline__ void mma_f16(float (&d)[4], const uint32_t (&a)[4],
                                        uint32_t b0, uint32_t b1) {
    asm volatile("mma.sync.aligned.m16n8k16.row.col.f32.f16.f16.f32 "
        "{%0,%1,%2,%3}, {%4,%5,%6,%7}, {%8,%9}, {%0,%1,%2,%3};"
        : "+f"(d[0]), "+f"(d[1]), "+f"(d[2]), "+f"(d[3])
        : "r"(a[0]), "r"(a[1]), "r"(a[2]), "r"(a[3]), "r"(b0), "r"(b1));
}
__device__ __forceinline__ unsigned long long pack_dup(float a) {
    unsigned long long r;
    asm("mov.b64 %0, {%1, %1};" : "=l"(r) : "f"(a));
    return r;
}
__device__ __forceinline__ void unpack2(unsigned long long v, float& lo, float& hi) {
    asm("mov.b64 {%0, %1}, %2;" : "=f"(lo), "=f"(hi) : "l"(v));
}
__device__ __forceinline__ void ffma2(unsigned long long& acc, unsigned long long a,
                                      unsigned long long b) {
    asm("fma.rn.f32x2 %0, %1, %2, %0;" : "+l"(acc) : "l"(a), "l"(b));
}

// ---------------- small math helpers ------------------------------------------
// pack two floats as f16x2 (v0 -> low half, v1 -> high half)
__device__ __forceinline__ uint32_t f16x2bits(float v0, float v1) {
    __half2 h = __floats2half2_rn(v0, v1);
    return *reinterpret_cast<uint32_t*>(&h);
}
__device__ __forceinline__ float softplusf(float x) {
    if (x > 20.f) return x;
    return log1pf(expf(x));
}

// ---------------- weight convert prologue (fp16) -------------------------------
__global__ __launch_bounds__(256)
void wsplit_kernel(const float* __restrict__ W2, const float* __restrict__ W3)
{
    int idx = blockIdx.x * 256 + threadIdx.x;     // 0..65535
    int layer = idx >> 15;
    int rem   = idx & 32767;
    int k  = rem >> 7;          // 0..255
    int nw = rem & 127;         // 0..127
    const float* W = layer ? W3 : W2;
    float v0 = W[k * 256 + nw * 2];
    float v1 = W[k * 256 + nw * 2 + 1];
    g_Wh[idx] = f16x2bits(v0, v1);
}

// ---------------- prologue: batched 1024x256 projection GEMM (f32x2) ----------
struct ProjJob {
    const float* A; const float* W; const float* bias; float* C;
    int wrow0; int doRelu; int doTrans;
};

__global__ __launch_bounds__(256)
void proj_batch_kernel(ProjJob j0, ProjJob j1, ProjJob j2, ProjJob j3, int K)
{
    ProjJob jb = (blockIdx.z == 0) ? j0 : (blockIdx.z == 1) ? j1 :
                 (blockIdx.z == 2) ? j2 : j3;
    __shared__ float As[16][36];
    __shared__ float Ws[16][68];
    const int tid = threadIdx.x;
    const int m0  = blockIdx.y * 32;
    const int n0  = blockIdx.x * 64;
    const int ty  = tid >> 4, tx = tid & 15;

    unsigned long long acc2[2][2] = {{0ull, 0ull}, {0ull, 0ull}};
    const int nch = K >> 4;
    for (int ch = 0; ch < nch; ch++) {
        const int kc = ch << 4;
        __syncthreads();
        {
            int e = tid;        int m = e >> 4, kk = e & 15;
            As[kk][m] = jb.A[(m0 + m) * K + kc + kk];
            e = tid + 256;      m = e >> 4;     kk = e & 15;
            As[kk][m] = jb.A[(m0 + m) * K + kc + kk];
        }
        #pragma unroll
        for (int i = 0; i < 4; i++) {
            int e = tid + (i << 8);
            int kk = e >> 6, n = e & 63;
            Ws[kk][n] = jb.W[(jb.wrow0 + kc + kk) * 256 + n0 + n];
        }
        __syncthreads();
        #pragma unroll
        for (int kk = 0; kk < 16; kk++) {
            unsigned long long a0d = pack_dup(As[kk][ty * 2]);
            unsigned long long a1d = pack_dup(As[kk][ty * 2 + 1]);
            unsigned long long w01 = *(const unsigned long long*)&Ws[kk][tx * 4];
            unsigned long long w23 = *(const unsigned long long*)&Ws[kk][tx * 4 + 2];
            ffma2(acc2[0][0], a0d, w01);
            ffma2(acc2[0][1], a0d, w23);
            ffma2(acc2[1][0], a1d, w01);
            ffma2(acc2[1][1], a1d, w23);
        }
    }
    #pragma unroll
    for (int i = 0; i < 2; i++) {
        float vout[4];
        unpack2(acc2[i][0], vout[0], vout[1]);
        unpack2(acc2[i][1], vout[2], vout[3]);
        const int r = m0 + ty * 2 + i;
        #pragma unroll
        for (int j = 0; j < 4; j++) {
            const int n = n0 + tx * 4 + j;
            float v = vout[j] + (jb.bias ? jb.bias[n] : 0.f);
            if (jb.doRelu) v = fmaxf(v, 0.f);
            if (jb.doTrans) jb.C[n * MR + r] = v;
            else            jb.C[r * 256 + n] = v;
        }
    }
}

// ---------------- main pairwise-MLP kernel (mma.sync fp16) ---------------------

// copy one 32-row k-chunk (16KB) into one of 4 smem buffers
__device__ __forceinline__ void cp_chunk(const char* __restrict__ srcH,
                                         uint32_t dstbase, int tid)
{
    #pragma unroll
    for (int i = 0; i < 2; i++) {
        int e = tid + i * 512;                 // 0..1023
        int k = e >> 5, u = e & 31;            // row, 16B unit
        uint32_t d = dstbase + (uint32_t)k * 512u + (uint32_t)((u ^ (k & 7)) << 4);
        asm volatile("cp.async.cg.shared.global [%0], [%1], 16;"
                     :: "r"(d), "l"(srcH + e * 16));
    }
    asm volatile("cp.async.commit_group;" ::: "memory");
}

// build 2 adjacent 16B units (g0, g0+1) of one A row: j0 = 8*g + quad*2
__device__ __forceinline__ void a_store_units(char* smp, int m, int quad, int g0,
                                              float v0, float v1, float v2, float v3)
{
    char* arow = smp + (uint32_t)m * 512u;
    uint32_t off0 = (uint32_t)(((g0 ^ (m & 7)) << 4) + quad * 4);
    *(uint32_t*)(arow + SM_AHI + off0) = f16x2bits(v0, v1);
    uint32_t off1 = (uint32_t)((((g0 + 1) ^ (m & 7)) << 4) + quad * 4);
    *(uint32_t*)(arow + SM_AHI + off1) = f16x2bits(v2, v3);
}

// One 128x256x256 fp16 GEMM: acc += A(fp16) @ B(fp16 stream).
// 4-stage cp.async pipeline: chunks 0,1,2 must be issued by the caller.
// FIRST: additionally builds A slice c+1 and accumulates the variance dot.
template<bool FIRST>
__device__ __forceinline__ void gemm_pass(uint32_t abase,
                                          const char* __restrict__ WhL,
                                          int warpM, int warpN, int lane, int tid,
                                          float (&acc)[2][8][4],
                                          char* smp, const float* __restrict__ qpb,
                                          const float* __restrict__ vqb,
                                          const float* __restrict__ wv2s,
                                          int rowb, float& vacc)
{
    const int rit  = (lane & 7) | (((lane >> 3) & 1) << 3); // row within 16-tile
    const int koff = lane >> 4;                              // 0/1: unit select
    const int quad = tid >> 7;                               // 0..3 (also p)
    const int m    = tid & 127;
    uint32_t a_row[2]; int a_sw[2];
    #pragma unroll
    for (int mt = 0; mt < 2; mt++) {
        int rr = warpM * 32 + mt * 16 + rit;
        a_row[mt] = abase + (uint32_t)rr * 512u;
        a_sw[mt]  = rr & 7;
    }
    const uint32_t wb = abase + SM_B;

    #pragma unroll 1
    for (int c = 0; c < 8; c++) {
        asm volatile("cp.async.wait_group 2;" ::: "memory");
        __syncthreads();
        if (c < 5)
            cp_chunk(WhL + (c + 3) * 16384,
                     wb + (uint32_t)(((c + 3) & 3) * 16384), tid);
        const uint32_t bbase = wb + (uint32_t)((c & 3) * 16384);
        #pragma unroll
        for (int s = 0; s < 2; s++) {
            // ---- early global loads (latency hidden behind MMAs) ----
            float kp0, kp1, kp2, kp3;
            float vk0, vk1, vk2, vk3;
            int j0 = 0, jv = 0;
            if (FIRST) {
                if (c < 7) {
                    int g0 = 4 * (c + 1) + 2 * s;
                    j0 = 8 * g0 + quad * 2;
                    kp0 = g_kpT[j0 * MR + rowb];
                    kp1 = g_kpT[(j0 + 1) * MR + rowb];
                    kp2 = g_kpT[(j0 + 8) * MR + rowb];
                    kp3 = g_kpT[(j0 + 9) * MR + rowb];
                }
                jv = 32 * c + 8 * quad + 4 * s;
                vk0 = g_vkT[jv * MR + rowb];
                vk1 = g_vkT[(jv + 1) * MR + rowb];
                vk2 = g_vkT[(jv + 2) * MR + rowb];
                vk3 = g_vkT[(jv + 3) * MR + rowb];
            }

            // ---- MMA work for k16 = 2c + s ----
            const int k16 = c * 2 + s;
            uint32_t ah[2][4];
            #pragma unroll
            for (int mt = 0; mt < 2; mt++) {
                uint32_t unit = (uint32_t)(k16 * 2 + koff);
                uint32_t o = ((unit ^ (uint32_t)a_sw[mt]) << 4);
                ldsm_x4(ah[mt], a_row[mt] + o);
            }
            const int kl = s * 16 + rit;
            const uint32_t brow = bbase + (uint32_t)kl * 512u;
            const uint32_t ksw = (uint32_t)(kl & 7);
            #pragma unroll
            for (int np = 0; np < 4; np++) {
                uint32_t bh[4];
                uint32_t nunit = (uint32_t)(warpN * 8 + np * 2 + koff);
                uint32_t o = ((nunit ^ ksw) << 4);
                ldsm_x4_t(bh, brow + o);
                #pragma unroll
                for (int mt = 0; mt < 2; mt++) {
                    mma_f16(acc[mt][np * 2],     ah[mt], bh[0], bh[1]);
                    mma_f16(acc[mt][np * 2 + 1], ah[mt], bh[2], bh[3]);
                }
            }

            // ---- late: A-build stores + variance FMAs ----
            if (FIRST) {
                if (c < 7) {
                    int g0 = 4 * (c + 1) + 2 * s;
                    float v0 = fmaxf(qpb[j0]     + kp0, 0.f);
                    float v1 = fmaxf(qpb[j0 + 1] + kp1, 0.f);
                    float v2 = fmaxf(qpb[j0 + 8] + kp2, 0.f);
                    float v3 = fmaxf(qpb[j0 + 9] + kp3, 0.f);
                    a_store_units(smp, m, quad, g0, v0, v1, v2, v3);
                }
                vacc = fmaf(fmaxf(vqb[jv]     + vk0, 0.f), wv2s[jv],     vacc);
                vacc = fmaf(fmaxf(vqb[jv + 1] + vk1, 0.f), wv2s[jv + 1], vacc);
                vacc = fmaf(fmaxf(vqb[jv + 2] + vk2, 0.f), wv2s[jv + 2], vacc);
                vacc = fmaf(fmaxf(vqb[jv + 3] + vk3, 0.f), wv2s[jv + 3], vacc);
            }
        }
    }
}

__global__ __launch_bounds__(512, 1)
void pair_mma_kernel(const float* __restrict__ b1,  const float* __restrict__ b2,
                     const float* __restrict__ b3,  const float* __restrict__ Wf,
                     const float* __restrict__ bfp, const float* __restrict__ bv1,
                     const float* __restrict__ Wv2, const float* __restrict__ bv2,
                     float* __restrict__ out)
{
    extern __shared__ char smraw[];
    const uint32_t smbase = smem_u32(smraw);
    const uint32_t abase  = (smbase + 1023u) & ~1023u;
    char* smp = smraw + (abase - smbase);
    float* qpb  = (float*)(smp + SM_VEC);
    float* vqb  = qpb + 256;
    float* b2s  = vqb + 256;
    float* b3s  = b2s + 256;
    float* wfs  = b3s + 256;
    float* wv2s = wfs + 256;
    float* red  = wv2s + 256;   // 512 floats: [row][warpN]
    float* vred = red + 512;    // 512 floats: [key][p]

    const int tid   = threadIdx.x;
    const int lane  = tid & 31;
    const int w     = tid >> 5;
    const int warpM = w & 3, warpN = w >> 2;
    const int quad  = tid >> 7;
    const int m     = tid & 127;
    const int bid = blockIdx.x;
    const int kt  = bid & 3;
    const int q   = (bid >> 2) & 511;
    const int b   = bid >> 11;
    const int k0  = kt << 7;
    const int rowb  = b * SKK + k0 + m;
    const int lbase = (b * SQ + q) * SKK + k0;

    // prefetch W2 chunks 0..2 immediately (4-stage pipeline prologue)
    cp_chunk((const char*)g_Wh,         abase + SM_B,          tid);
    cp_chunk((const char*)g_Wh + 16384, abase + SM_B + 16384u, tid);
    cp_chunk((const char*)g_Wh + 32768, abase + SM_B + 32768u, tid);

    // vectors
    {
        const int r = (b * SQ + q) * HH;
        if (tid < 256) {
            qpb[tid] = g_qp[r + tid] + b1[tid];
            b2s[tid] = b2[tid];
            wfs[tid] = Wf[tid];
        } else {
            int u = tid & 255;
            vqb[u]  = g_vq[r + u] + bv1[u];
            b3s[u]  = b3[u];
            wv2s[u] = Wv2[u];
        }
    }
    __syncthreads();

    // ---- prebuild A slice 0 only (units g=0..3); slices 1..7 built in-loop ----
    {
        #pragma unroll
        for (int gg = 0; gg < 2; gg++) {
            int g0 = gg * 2;
            int j0 = 8 * g0 + quad * 2;
            float v0 = fmaxf(qpb[j0]     + g_kpT[j0 * MR + rowb],       0.f);
            float v1 = fmaxf(qpb[j0 + 1] + g_kpT[(j0 + 1) * MR + rowb], 0.f);
            float v2 = fmaxf(qpb[j0 + 8] + g_kpT[(j0 + 8) * MR + rowb], 0.f);
            float v3 = fmaxf(qpb[j0 + 9] + g_kpT[(j0 + 9) * MR + rowb], 0.f);
            a_store_units(smp, m, quad, g0, v0, v1, v2, v3);
        }
    }

    // ---- GEMM 1: D = h0 @ W2 (A-build + variance interleaved) ----
    float acc[2][8][4];
    #pragma unroll
    for (int i = 0; i < 2; i++)
        #pragma unroll
        for (int j = 0; j < 8; j++)
            #pragma unroll
            for (int e = 0; e < 4; e++) acc[i][j][e] = 0.f;
    float vacc = 0.f;
    gemm_pass<true>(abase, (const char*)g_Wh,
                    warpM, warpN, lane, tid, acc,
                    smp, qpb, vqb, wv2s, rowb, vacc);
    vred[m * 4 + quad] = vacc;
    __syncthreads();   // all readers of h0 done; vred complete; B bufs free

    // prefetch W3 chunks 0..2 (overlaps epilogue 1)
    cp_chunk((const char*)g_Wh + 131072,         abase + SM_B,          tid);
    cp_chunk((const char*)g_Wh + 131072 + 16384, abase + SM_B + 16384u, tid);
    cp_chunk((const char*)g_Wh + 131072 + 32768, abase + SM_B + 32768u, tid);

    // variance finalize
    if (tid < 128) {
        float s = vred[tid * 4] + vred[tid * 4 + 1] + vred[tid * 4 + 2] + vred[tid * 4 + 3]
                  + bv2[0];
        out[NTOT + lbase + tid] = softplusf(s);
    }

    // ---- epilogue 1: h1 = relu(D + b2) -> A buffer (fp16) ----
    {
        const int g  = lane >> 2;
        const int tg = lane & 3;
        #pragma unroll
        for (int mt = 0; mt < 2; mt++) {
            int r0 = warpM * 32 + mt * 16 + g;
            int r1 = r0 + 8;
            uint32_t row0 = (uint32_t)r0 * 512u;
            uint32_t row1 = (uint32_t)r1 * 512u;
            #pragma unroll
            for (int nt = 0; nt < 8; nt++) {
                int c0 = warpN * 64 + nt * 8 + tg * 2;
                float b20 = b2s[c0], b21 = b2s[c0 + 1];
                float v00 = fmaxf(acc[mt][nt][0] + b20, 0.f);
                float v01 = fmaxf(acc[mt][nt][1] + b21, 0.f);
                float v10 = fmaxf(acc[mt][nt][2] + b20, 0.f);
                float v11 = fmaxf(acc[mt][nt][3] + b21, 0.f);
                uint32_t unit = (uint32_t)(c0 >> 3);
                uint32_t o0 = row0 + ((unit ^ (uint32_t)(r0 & 7)) << 4) + (uint32_t)(tg * 4);
                uint32_t o1 = row1 + ((unit ^ (uint32_t)(r1 & 7)) << 4) + (uint32_t)(tg * 4);
                *(uint32_t*)(smp + SM_AHI + o0) = f16x2bits(v00, v01);
                *(uint32_t*)(smp + SM_AHI + o1) = f16x2bits(v10, v11);
            }
        }
    }
    __syncthreads();

    // ---- GEMM 2: D = h1 @ W3 ----
    #pragma unroll
    for (int i = 0; i < 2; i++)
        #pragma unroll
        for (int j = 0; j < 8; j++)
            #pragma unroll
            for (int e = 0; e < 4; e++) acc[i][j][e] = 0.f;
    gemm_pass<false>(abase, (const char*)g_Wh + 131072,
                     warpM, warpN, lane, tid, acc,
                     smp, qpb, vqb, wv2s, rowb, vacc);

    // ---- epilogue 2: logit = relu(D + b3) . Wf, cross-warp reduce ----
    {
        const int g  = lane >> 2;
        const int tg = lane & 3;
        #pragma unroll
        for (int mt = 0; mt < 2; mt++) {
            float lg0 = 0.f, lg1 = 0.f;
            #pragma unroll
            for (int nt = 0; nt < 8; nt++) {
                int c0 = warpN * 64 + nt * 8 + tg * 2;
                float b30 = b3s[c0], b31 = b3s[c0 + 1];
                float w0  = wfs[c0], w1  = wfs[c0 + 1];
                lg0 = fmaf(fmaxf(acc[mt][nt][0] + b30, 0.f), w0, lg0);
                lg0 = fmaf(fmaxf(acc[mt][nt][1] + b31, 0.f), w1, lg0);
                lg1 = fmaf(fmaxf(acc[mt][nt][2] + b30, 0.f), w0, lg1);
                lg1 = fmaf(fmaxf(acc[mt][nt][3] + b31, 0.f), w1, lg1);
            }
            lg0 += __shfl_xor_sync(0xffffffffu, lg0, 1);
            lg0 += __shfl_xor_sync(0xffffffffu, lg0, 2);
            lg1 += __shfl_xor_sync(0xffffffffu, lg1, 1);
            lg1 += __shfl_xor_sync(0xffffffffu, lg1, 2);
            if (tg == 0) {
                int r0 = warpM * 32 + mt * 16 + g;
                red[r0 * 4 + warpN]       = lg0;
                red[(r0 + 8) * 4 + warpN] = lg1;
            }
        }
    }
    __syncthreads();
    if (tid < 128) {
        float s = red[tid * 4] + red[tid * 4 + 1] + red[tid * 4 + 2] + red[tid * 4 + 3]
                  + bfp[0];
        out[lbase + tid] = s;
    }
}

// ---------------- launcher -----------------------------------------------------
extern "C" void kernel_launch(void* const* d_in, const int* in_sizes, int n_in,
                              void* d_out, int out_size)
{
    const float* query = (const float*)d_in[0];
    const float* key   = (const float*)d_in[1];
    const float* Wqe   = (const float*)d_in[2];
    const float* bqe   = (const float*)d_in[3];
    const float* Wke   = (const float*)d_in[4];
    const float* bke   = (const float*)d_in[5];
    const float* W1    = (const float*)d_in[6];
    const float* b1    = (const float*)d_in[7];
    const float* W2    = (const float*)d_in[8];
    const float* b2    = (const float*)d_in[9];
    const float* W3    = (const float*)d_in[10];
    const float* b3    = (const float*)d_in[11];
    const float* Wf    = (const float*)d_in[12];
    const float* bf    = (const float*)d_in[13];
    const float* Wv1   = (const float*)d_in[14];
    const float* bv1   = (const float*)d_in[15];
    const float* Wv2   = (const float*)d_in[16];
    const float* bv2   = (const float*)d_in[17];
    float* out = (float*)d_out;

    void *p_qf, *p_kf, *p_qp, *p_vq, *p_kpT, *p_vkT;
    cudaGetSymbolAddress(&p_qf,  g_qf);
    cudaGetSymbolAddress(&p_kf,  g_kf);
    cudaGetSymbolAddress(&p_qp,  g_qp);
    cudaGetSymbolAddress(&p_vq,  g_vq);
    cudaGetSymbolAddress(&p_kpT, g_kpT);
    cudaGetSymbolAddress(&p_vkT, g_vkT);

    // weight convert (independent of projections)
    wsplit_kernel<<<256, 256>>>(W2, W3);

    // encoders: qf = relu(query@Wqe+bqe), kf = relu(key@Wke+bke)
    ProjJob e0 { query, Wqe, bqe, (float*)p_qf, 0, 1, 0 };
    ProjJob e1 { key,   Wke, bke, (float*)p_kf, 0, 1, 0 };
    proj_batch_kernel<<<dim3(4, 32, 2), 256>>>(e0, e1, e0, e0, EE);

    // stage-2 projections
    ProjJob s0 { (const float*)p_qf, W1,  nullptr, (float*)p_qp,  0,   0, 0 };
    ProjJob s1 { (const float*)p_kf, W1,  nullptr, (float*)p_kpT, 256, 0, 1 };
    ProjJob s2 { (const float*)p_qf, Wv1, nullptr, (float*)p_vq,  0,   0, 0 };
    ProjJob s3 { (const float*)p_kf, Wv1, nullptr, (float*)p_vkT, 256, 0, 1 };
    proj_batch_kernel<<<dim3(4, 32, 4), 256>>>(s0, s1, s2, s3, HH);

    // main fused pairwise-MLP kernel (mma.sync fp16)
    cudaFuncSetAttribute(pair_mma_kernel,
                         cudaFuncAttributeMaxDynamicSharedMemorySize, SMEM_BYTES);
    pair_mma_kernel<<<BB * SQ * (SKK / 128), 512, SMEM_BYTES>>>(
        b1, b2, b3, Wf, bf, bv1, Wv2, bv2, out);
}

// round 8
// speedup vs baseline: 5.1338x; 1.0122x over previous
#include <cuda_runtime.h>
#include <cuda_bf16.h>
#include <cuda_fp16.h>
#include <math.h>
#include <stdint.h>

// Problem dims (fixed)
#define BB   2
#define SQ   512
#define SKK  512
#define EE   512
#define HH   256
#define MR   1024            // B*SQ = B*SK
#define NTOT (BB*SQ*SKK)     // 524288

// ---------------- scratch (device globals; no allocation allowed) -------------
__device__ float g_qf [MR*HH];
__device__ float g_kf [MR*HH];
__device__ float g_qp [MR*HH];
__device__ float g_vq [MR*HH];
__device__ float g_kpT[HH*MR];   // [H][B*SK]
__device__ float g_vkT[HH*MR];   // [H][B*SK]
// fp16 weight images: word layout [layer][k][nw] (nw = n/2, f16x2)
__device__ __align__(16) uint32_t g_Wh[2 * 256 * 128];

// SMEM map (byte offsets from 1024-aligned base)
#define SM_AHI 0u        // 128 rows x 512B  (fp16 A)
#define SM_B   65536u    // 4 bufs x 16KB
#define SM_VEC 131072u
#define SMEM_BYTES (141312 + 1024)

// ---------------- PTX helpers --------------------------------------------------
__device__ __forceinline__ uint32_t smem_u32(const void* p) {
    return (uint32_t)__cvta_generic_to_shared(p);
}
__device__ __forceinline__ void ldsm_x4(uint32_t (&r)[4], uint32_t addr) {
    asm volatile("ldmatrix.sync.aligned.m8n8.x4.shared.b16 {%0,%1,%2,%3}, [%4];"
        : "=r"(r[0]), "=r"(r[1]), "=r"(r[2]), "=r"(r[3]) : "r"(addr));
}
__device__ __forceinline__ void ldsm_x4_t(uint32_t (&r)[4], uint32_t addr) {
    asm volatile("ldmatrix.sync.aligned.m8n8.x4.trans.shared.b16 {%0,%1,%2,%3}, [%4];"
        : "=r"(r[0]), "=r"(r[1]), "=r"(r[2]), "=r"(r[3]) : "r"(addr));
}
__device__ __forceinline__ void mma_f16(float (&d)[4], const uint32_t (&a)[4],
                                        uint32_t b0, uint32_t b1) {
    asm volatile("mma.sync.aligned.m16n8k16.row.col.f32.f16.f16.f32 "
        "{%0,%1,%2,%3}, {%4,%5,%6,%7}, {%8,%9}, {%0,%1,%2,%3};"
        : "+f"(d[0]), "+f"(d[1]), "+f"(d[2]), "+f"(d[3])
        : "r"(a[0]), "r"(a[1]), "r"(a[2]), "r"(a[3]), "r"(b0), "r"(b1));
}
__device__ __forceinline__ unsigned long long pack_dup(float a) {
    unsigned long long r;
    asm("mov.b64 %0, {%1, %1};" : "=l"(r) : "f"(a));
    return r;
}
__device__ __forceinline__ void unpack2(unsigned long long v, float& lo, float& hi) {
    asm("mov.b64 {%0, %1}, %2;" : "=f"(lo), "=f"(hi) : "l"(v));
}
__device__ __forceinline__ void ffma2(unsigned long long& acc, unsigned long long a,
                                      unsigned long long b) {
    asm("fma.rn.f32x2 %0, %1, %2, %0;" : "+l"(acc) : "l"(a), "l"(b));
}

// ---------------- small math helpers ------------------------------------------
// pack two floats as f16x2 (v0 -> low half, v1 -> high half)
__device__ __forceinline__ uint32_t f16x2bits(float v0, float v1) {
    __half2 h = __floats2half2_rn(v0, v1);
    return *reinterpret_cast<uint32_t*>(&h);
}
__device__ __forceinline__ float softplusf(float x) {
    if (x > 20.f) return x;
    return log1pf(expf(x));
}

// ---------------- weight convert prologue (fp16) -------------------------------
__global__ __launch_bounds__(256)
void wsplit_kernel(const float* __restrict__ W2, const float* __restrict__ W3)
{
    int idx = blockIdx.x * 256 + threadIdx.x;     // 0..65535
    int layer = idx >> 15;
    int rem   = idx & 32767;
    int k  = rem >> 7;          // 0..255
    int nw = rem & 127;         // 0..127
    const float* W = layer ? W3 : W2;
    float v0 = W[k * 256 + nw * 2];
    float v1 = W[k * 256 + nw * 2 + 1];
    g_Wh[idx] = f16x2bits(v0, v1);
}

// ---------------- prologue: batched 1024x256 projection GEMM (f32x2) ----------
struct ProjJob {
    const float* A; const float* W; const float* bias; float* C;
    int wrow0; int doRelu; int doTrans;
};

__global__ __launch_bounds__(256)
void proj_batch_kernel(ProjJob j0, ProjJob j1, ProjJob j2, ProjJob j3, int K)
{
    ProjJob jb = (blockIdx.z == 0) ? j0 : (blockIdx.z == 1) ? j1 :
                 (blockIdx.z == 2) ? j2 : j3;
    __shared__ float As[16][36];
    __shared__ float Ws[16][68];
    const int tid = threadIdx.x;
    const int m0  = blockIdx.y * 32;
    const int n0  = blockIdx.x * 64;
    const int ty  = tid >> 4, tx = tid & 15;

    unsigned long long acc2[2][2] = {{0ull, 0ull}, {0ull, 0ull}};
    const int nch = K >> 4;
    for (int ch = 0; ch < nch; ch++) {
        const int kc = ch << 4;
        __syncthreads();
        {
            int e = tid;        int m = e >> 4, kk = e & 15;
            As[kk][m] = jb.A[(m0 + m) * K + kc + kk];
            e = tid + 256;      m = e >> 4;     kk = e & 15;
            As[kk][m] = jb.A[(m0 + m) * K + kc + kk];
        }
        #pragma unroll
        for (int i = 0; i < 4; i++) {
            int e = tid + (i << 8);
            int kk = e >> 6, n = e & 63;
            Ws[kk][n] = jb.W[(jb.wrow0 + kc + kk) * 256 + n0 + n];
        }
        __syncthreads();
        #pragma unroll
        for (int kk = 0; kk < 16; kk++) {
            unsigned long long a0d = pack_dup(As[kk][ty * 2]);
            unsigned long long a1d = pack_dup(As[kk][ty * 2 + 1]);
            unsigned long long w01 = *(const unsigned long long*)&Ws[kk][tx * 4];
            unsigned long long w23 = *(const unsigned long long*)&Ws[kk][tx * 4 + 2];
            ffma2(acc2[0][0], a0d, w01);
            ffma2(acc2[0][1], a0d, w23);
            ffma2(acc2[1][0], a1d, w01);
            ffma2(acc2[1][1], a1d, w23);
        }
    }
    #pragma unroll
    for (int i = 0; i < 2; i++) {
        float vout[4];
        unpack2(acc2[i][0], vout[0], vout[1]);
        unpack2(acc2[i][1], vout[2], vout[3]);
        const int r = m0 + ty * 2 + i;
        #pragma unroll
        for (int j = 0; j < 4; j++) {
            const int n = n0 + tx * 4 + j;
            float v = vout[j] + (jb.bias ? jb.bias[n] : 0.f);
            if (jb.doRelu) v = fmaxf(v, 0.f);
            if (jb.doTrans) jb.C[n * MR + r] = v;
            else            jb.C[r * 256 + n] = v;
        }
    }
}

// ---------------- main pairwise-MLP kernel (mma.sync fp16, reg-pipelined) ------

// copy one 32-row k-chunk (16KB) into one of 4 smem buffers
__device__ __forceinline__ void cp_chunk(const char* __restrict__ srcH,
                                         uint32_t dstbase, int tid)
{
    #pragma unroll
    for (int i = 0; i < 2; i++) {
        int e = tid + i * 512;                 // 0..1023
        int k = e >> 5, u = e & 31;            // row, 16B unit
        uint32_t d = dstbase + (uint32_t)k * 512u + (uint32_t)((u ^ (k & 7)) << 4);
        asm volatile("cp.async.cg.shared.global [%0], [%1], 16;"
                     :: "r"(d), "l"(srcH + e * 16));
    }
    asm volatile("cp.async.commit_group;" ::: "memory");
}

// build 2 adjacent 16B units (g0, g0+1) of one A row: j0 = 8*g + quad*2
__device__ __forceinline__ void a_store_units(char* smp, int m, int quad, int g0,
                                              float v0, float v1, float v2, float v3)
{
    char* arow = smp + (uint32_t)m * 512u;
    uint32_t off0 = (uint32_t)(((g0 ^ (m & 7)) << 4) + quad * 4);
    *(uint32_t*)(arow + SM_AHI + off0) = f16x2bits(v0, v1);
    uint32_t off1 = (uint32_t)((((g0 + 1) ^ (m & 7)) << 4) + quad * 4);
    *(uint32_t*)(arow + SM_AHI + off1) = f16x2bits(v2, v3);
}

// One 128x256x256 fp16 GEMM: acc += A(fp16) @ B(fp16 stream).
// Register-pipelined fragments; 4-stage cp.async (caller pre-issued chunks 0..2).
// FIRST: builds A slice for chunk c+2 and accumulates the variance dot in-loop.
template<bool FIRST>
__device__ __forceinline__ void gemm_pass(uint32_t abase,
                                          const char* __restrict__ WhL,
                                          int warpM, int warpN, int lane, int tid,
                                          float (&acc)[2][8][4],
                                          char* smp, const float* __restrict__ qpb,
                                          const float* __restrict__ vqb,
                                          const float* __restrict__ wv2s,
                                          int rowb, float& vacc)
{
    const int rit  = (lane & 7) | (((lane >> 3) & 1) << 3); // row within 16-tile
    const int koff = lane >> 4;                              // 0/1: unit select
    const int quad = tid >> 7;                               // 0..3 (also p)
    const int m    = tid & 127;
    uint32_t a_row[2]; uint32_t a_sw[2];
    #pragma unroll
    for (int mt = 0; mt < 2; mt++) {
        int rr = warpM * 32 + mt * 16 + rit;
        a_row[mt] = abase + (uint32_t)rr * 512u;
        a_sw[mt]  = (uint32_t)(rr & 7);
    }
    const uint32_t wb = abase + SM_B;
    const uint32_t ksw = (uint32_t)(rit & 7);
    uint32_t boff[4];
    #pragma unroll
    for (int np = 0; np < 4; np++) {
        uint32_t nunit = (uint32_t)(warpN * 8 + np * 2 + koff);
        boff[np] = ((nunit ^ ksw) << 4);
    }
    const uint32_t browbase = wb + (uint32_t)rit * 512u;

    // top of chunk 0 (groups 0,1,2 were issued by the caller)
    asm volatile("cp.async.wait_group 1;" ::: "memory");   // chunks 0,1 ready
    __syncthreads();
    cp_chunk(WhL + 3 * 16384, wb + (uint32_t)(3 * 16384), tid);

    // fragment double buffers: parity = k16 & 1 (== s)
    uint32_t aF[2][2][4];   // [parity][mt]
    uint32_t bF[2][2][4];   // [parity][np 0..1]
    {
        #pragma unroll
        for (int mt = 0; mt < 2; mt++) {
            uint32_t unit = (uint32_t)koff;                 // k16 = 0
            ldsm_x4(aF[0][mt], a_row[mt] + ((unit ^ a_sw[mt]) << 4));
        }
        ldsm_x4_t(bF[0][0], browbase + boff[0]);            // buf 0, s=0
        ldsm_x4_t(bF[0][1], browbase + boff[1]);
    }

    #pragma unroll 1
    for (int c = 0; c < 8; c++) {
        if (c > 0) {
            if (c <= 5) { asm volatile("cp.async.wait_group 1;" ::: "memory"); }
            else        { asm volatile("cp.async.wait_group 0;" ::: "memory"); }
            __syncthreads();
            if (c <= 4)
                cp_chunk(WhL + (c + 3) * 16384,
                         wb + (uint32_t)(((c + 3) & 3) * 16384), tid);
        }
        const uint32_t bb_cur = (uint32_t)((c & 3) * 16384);
        #pragma unroll
        for (int s = 0; s < 2; s++) {
            // ---- early global loads (latency hidden behind MMAs) ----
            float kp0, kp1, kp2, kp3;
            float vk0, vk1, vk2, vk3;
            int j0 = 0, jv = 0;
            if (FIRST) {
                if (c < 6) {           // build A slice for chunk c+2
                    int g0 = 4 * (c + 2) + 2 * s;
                    j0 = 8 * g0 + quad * 2;
                    kp0 = g_kpT[j0 * MR + rowb];
                    kp1 = g_kpT[(j0 + 1) * MR + rowb];
                    kp2 = g_kpT[(j0 + 8) * MR + rowb];
                    kp3 = g_kpT[(j0 + 9) * MR + rowb];
                }
                jv = 32 * c + 8 * quad + 4 * s;
                vk0 = g_vkT[jv * MR + rowb];
                vk1 = g_vkT[(jv + 1) * MR + rowb];
                vk2 = g_vkT[(jv + 2) * MR + rowb];
                vk3 = g_vkT[(jv + 3) * MR + rowb];
            }

            // ---- B np=2,3 for current k16 ----
            uint32_t bT[2][4];
            uint32_t brow = browbase + bb_cur + (uint32_t)(s * 8192);
            ldsm_x4_t(bT[0], brow + boff[2]);
            ldsm_x4_t(bT[1], brow + boff[3]);

            // ---- MMA np=0,1 with pre-loaded fragments ----
            #pragma unroll
            for (int mt = 0; mt < 2; mt++) {
                mma_f16(acc[mt][0], aF[s][mt], bF[s][0][0], bF[s][0][1]);
                mma_f16(acc[mt][1], aF[s][mt], bF[s][0][2], bF[s][0][3]);
                mma_f16(acc[mt][2], aF[s][mt], bF[s][1][0], bF[s][1][1]);
                mma_f16(acc[mt][3], aF[s][mt], bF[s][1][2], bF[s][1][3]);
            }

            // ---- prefetch fragments for k16+1 ----
            if (!(c == 7 && s == 1)) {
                int k16n = c * 2 + s + 1;
                int cn = k16n >> 1, sn = k16n & 1;
                #pragma unroll
                for (int mt = 0; mt < 2; mt++) {
                    uint32_t unit = (uint32_t)(k16n * 2 + koff);
                    ldsm_x4(aF[s ^ 1][mt], a_row[mt] + ((unit ^ a_sw[mt]) << 4));
                }
                uint32_t brown = browbase + (uint32_t)((cn & 3) * 16384)
                                          + (uint32_t)(sn * 8192);
                ldsm_x4_t(bF[s ^ 1][0], brown + boff[0]);
                ldsm_x4_t(bF[s ^ 1][1], brown + boff[1]);
            }

            // ---- MMA np=2,3 ----
            #pragma unroll
            for (int mt = 0; mt < 2; mt++) {
                mma_f16(acc[mt][4], aF[s][mt], bT[0][0], bT[0][1]);
                mma_f16(acc[mt][5], aF[s][mt], bT[0][2], bT[0][3]);
                mma_f16(acc[mt][6], aF[s][mt], bT[1][0], bT[1][1]);
                mma_f16(acc[mt][7], aF[s][mt], bT[1][2], bT[1][3]);
            }

            // ---- late: A-build stores + variance FMAs ----
            if (FIRST) {
                if (c < 6) {
                    int g0 = 4 * (c + 2) + 2 * s;
                    float v0 = fmaxf(qpb[j0]     + kp0, 0.f);
                    float v1 = fmaxf(qpb[j0 + 1] + kp1, 0.f);
                    float v2 = fmaxf(qpb[j0 + 8] + kp2, 0.f);
                    float v3 = fmaxf(qpb[j0 + 9] + kp3, 0.f);
                    a_store_units(smp, m, quad, g0, v0, v1, v2, v3);
                }
                vacc = fmaf(fmaxf(vqb[jv]     + vk0, 0.f), wv2s[jv],     vacc);
                vacc = fmaf(fmaxf(vqb[jv + 1] + vk1, 0.f), wv2s[jv + 1], vacc);
                vacc = fmaf(fmaxf(vqb[jv + 2] + vk2, 0.f), wv2s[jv + 2], vacc);
                vacc = fmaf(fmaxf(vqb[jv + 3] + vk3, 0.f), wv2s[jv + 3], vacc);
            }
        }
    }
}

__global__ __launch_bounds__(512, 1)
void pair_mma_kernel(const float* __restrict__ b1,  const float* __restrict__ b2,
                     const float* __restrict__ b3,  const float* __restrict__ Wf,
                     const float* __restrict__ bfp, const float* __restrict__ bv1,
                     const float* __restrict__ Wv2, const float* __restrict__ bv2,
                     float* __restrict__ out)
{
    extern __shared__ char smraw[];
    const uint32_t smbase = smem_u32(smraw);
    const uint32_t abase  = (smbase + 1023u) & ~1023u;
    char* smp = smraw + (abase - smbase);
    float* qpb  = (float*)(smp + SM_VEC);
    float* vqb  = qpb + 256;
    float* b2s  = vqb + 256;
    float* b3s  = b2s + 256;
    float* wfs  = b3s + 256;
    float* wv2s = wfs + 256;
    float* red  = wv2s + 256;   // 512 floats: [row][warpN]
    float* vred = red + 512;    // 512 floats: [key][p]

    const int tid   = threadIdx.x;
    const int lane  = tid & 31;
    const int w     = tid >> 5;
    const int warpM = w & 3, warpN = w >> 2;
    const int quad  = tid >> 7;
    const int m     = tid & 127;
    const int bid = blockIdx.x;
    const int kt  = bid & 3;
    const int q   = (bid >> 2) & 511;
    const int b   = bid >> 11;
    const int k0  = kt << 7;
    const int rowb  = b * SKK + k0 + m;
    const int lbase = (b * SQ + q) * SKK + k0;

    // prefetch W2 chunks 0..2 immediately (pipeline prologue)
    cp_chunk((const char*)g_Wh,         abase + SM_B,          tid);
    cp_chunk((const char*)g_Wh + 16384, abase + SM_B + 16384u, tid);
    cp_chunk((const char*)g_Wh + 32768, abase + SM_B + 32768u, tid);

    // vectors
    {
        const int r = (b * SQ + q) * HH;
        if (tid < 256) {
            qpb[tid] = g_qp[r + tid] + b1[tid];
            b2s[tid] = b2[tid];
            wfs[tid] = Wf[tid];
        } else {
            int u = tid & 255;
            vqb[u]  = g_vq[r + u] + bv1[u];
            b3s[u]  = b3[u];
            wv2s[u] = Wv2[u];
        }
    }
    __syncthreads();

    // ---- prebuild A slices for chunks 0 and 1 (units g=0..7) ----
    {
        #pragma unroll
        for (int gg = 0; gg < 4; gg++) {
            int g0 = gg * 2;
            int j0 = 8 * g0 + quad * 2;
            float v0 = fmaxf(qpb[j0]     + g_kpT[j0 * MR + rowb],       0.f);
            float v1 = fmaxf(qpb[j0 + 1] + g_kpT[(j0 + 1) * MR + rowb], 0.f);
            float v2 = fmaxf(qpb[j0 + 8] + g_kpT[(j0 + 8) * MR + rowb], 0.f);
            float v3 = fmaxf(qpb[j0 + 9] + g_kpT[(j0 + 9) * MR + rowb], 0.f);
            a_store_units(smp, m, quad, g0, v0, v1, v2, v3);
        }
    }

    // ---- GEMM 1: D = h0 @ W2 (A-build + variance interleaved) ----
    float acc[2][8][4];
    #pragma unroll
    for (int i = 0; i < 2; i++)
        #pragma unroll
        for (int j = 0; j < 8; j++)
            #pragma unroll
            for (int e = 0; e < 4; e++) acc[i][j][e] = 0.f;
    float vacc = 0.f;
    gemm_pass<true>(abase, (const char*)g_Wh,
                    warpM, warpN, lane, tid, acc,
                    smp, qpb, vqb, wv2s, rowb, vacc);
    vred[m * 4 + quad] = vacc;
    __syncthreads();   // all readers of h0 done; vred complete; B bufs free

    // prefetch W3 chunks 0..2 (overlaps epilogue 1)
    cp_chunk((const char*)g_Wh + 131072,         abase + SM_B,          tid);
    cp_chunk((const char*)g_Wh + 131072 + 16384, abase + SM_B + 16384u, tid);
    cp_chunk((const char*)g_Wh + 131072 + 32768, abase + SM_B + 32768u, tid);

    // variance finalize
    if (tid < 128) {
        float s = vred[tid * 4] + vred[tid * 4 + 1] + vred[tid * 4 + 2] + vred[tid * 4 + 3]
                  + bv2[0];
        out[NTOT + lbase + tid] = softplusf(s);
    }

    // ---- epilogue 1: h1 = relu(D + b2) -> A buffer (fp16) ----
    {
        const int g  = lane >> 2;
        const int tg = lane & 3;
        #pragma unroll
        for (int mt = 0; mt < 2; mt++) {
            int r0 = warpM * 32 + mt * 16 + g;
            int r1 = r0 + 8;
            uint32_t row0 = (uint32_t)r0 * 512u;
            uint32_t row1 = (uint32_t)r1 * 512u;
            #pragma unroll
            for (int nt = 0; nt < 8; nt++) {
                int c0 = warpN * 64 + nt * 8 + tg * 2;
                float b20 = b2s[c0], b21 = b2s[c0 + 1];
                float v00 = fmaxf(acc[mt][nt][0] + b20, 0.f);
                float v01 = fmaxf(acc[mt][nt][1] + b21, 0.f);
                float v10 = fmaxf(acc[mt][nt][2] + b20, 0.f);
                float v11 = fmaxf(acc[mt][nt][3] + b21, 0.f);
                uint32_t unit = (uint32_t)(c0 >> 3);
                uint32_t o0 = row0 + ((unit ^ (uint32_t)(r0 & 7)) << 4) + (uint32_t)(tg * 4);
                uint32_t o1 = row1 + ((unit ^ (uint32_t)(r1 & 7)) << 4) + (uint32_t)(tg * 4);
                *(uint32_t*)(smp + SM_AHI + o0) = f16x2bits(v00, v01);
                *(uint32_t*)(smp + SM_AHI + o1) = f16x2bits(v10, v11);
            }
        }
    }
    __syncthreads();

    // ---- GEMM 2: D = h1 @ W3 ----
    #pragma unroll
    for (int i = 0; i < 2; i++)
        #pragma unroll
        for (int j = 0; j < 8; j++)
            #pragma unroll
            for (int e = 0; e < 4; e++) acc[i][j][e] = 0.f;
    gemm_pass<false>(abase, (const char*)g_Wh + 131072,
                     warpM, warpN, lane, tid, acc,
                     smp, qpb, vqb, wv2s, rowb, vacc);

    // ---- epilogue 2: logit = relu(D + b3) . Wf, cross-warp reduce ----
    {
        const int g  = lane >> 2;
        const int tg = lane & 3;
        #pragma unroll
        for (int mt = 0; mt < 2; mt++) {
            float lg0 = 0.f, lg1 = 0.f;
            #pragma unroll
            for (int nt = 0; nt < 8; nt++) {
                int c0 = warpN * 64 + nt * 8 + tg * 2;
                float b30 = b3s[c0], b31 = b3s[c0 + 1];
                float w0  = wfs[c0], w1  = wfs[c0 + 1];
                lg0 = fmaf(fmaxf(acc[mt][nt][0] + b30, 0.f), w0, lg0);
                lg0 = fmaf(fmaxf(acc[mt][nt][1] + b31, 0.f), w1, lg0);
                lg1 = fmaf(fmaxf(acc[mt][nt][2] + b30, 0.f), w0, lg1);
                lg1 = fmaf(fmaxf(acc[mt][nt][3] + b31, 0.f), w1, lg1);
            }
            lg0 += __shfl_xor_sync(0xffffffffu, lg0, 1);
            lg0 += __shfl_xor_sync(0xffffffffu, lg0, 2);
            lg1 += __shfl_xor_sync(0xffffffffu, lg1, 1);
            lg1 += __shfl_xor_sync(0xffffffffu, lg1, 2);
            if (tg == 0) {
                int r0 = warpM * 32 + mt * 16 + g;
                red[r0 * 4 + warpN]       = lg0;
                red[(r0 + 8) * 4 + warpN] = lg1;
            }
        }
    }
    __syncthreads();
    if (tid < 128) {
        float s = red[tid * 4] + red[tid * 4 + 1] + red[tid * 4 + 2] + red[tid * 4 + 3]
                  + bfp[0];
        out[lbase + tid] = s;
    }
}

// ---------------- launcher -----------------------------------------------------
extern "C" void kernel_launch(void* const* d_in, const int* in_sizes, int n_in,
                              void* d_out, int out_size)
{
    const float* query = (const float*)d_in[0];
    const float* key   = (const float*)d_in[1];
    const float* Wqe   = (const float*)d_in[2];
    const float* bqe   = (const float*)d_in[3];
    const float* Wke   = (const float*)d_in[4];
    const float* bke   = (const float*)d_in[5];
    const float* W1    = (const float*)d_in[6];
    const float* b1    = (const float*)d_in[7];
    const float* W2    = (const float*)d_in[8];
    const float* b2    = (const float*)d_in[9];
    const float* W3    = (const float*)d_in[10];
    const float* b3    = (const float*)d_in[11];
    const float* Wf    = (const float*)d_in[12];
    const float* bf    = (const float*)d_in[13];
    const float* Wv1   = (const float*)d_in[14];
    const float* bv1   = (const float*)d_in[15];
    const float* Wv2   = (const float*)d_in[16];
    const float* bv2   = (const float*)d_in[17];
    float* out = (float*)d_out;

    void *p_qf, *p_kf, *p_qp, *p_vq, *p_kpT, *p_vkT;
    cudaGetSymbolAddress(&p_qf,  g_qf);
    cudaGetSymbolAddress(&p_kf,  g_kf);
    cudaGetSymbolAddress(&p_qp,  g_qp);
    cudaGetSymbolAddress(&p_vq,  g_vq);
    cudaGetSymbolAddress(&p_kpT, g_kpT);
    cudaGetSymbolAddress(&p_vkT, g_vkT);

    // weight convert (independent of projections)
    wsplit_kernel<<<256, 256>>>(W2, W3);

    // encoders: qf = relu(query@Wqe+bqe), kf = relu(key@Wke+bke)
    ProjJob e0 { query, Wqe, bqe, (float*)p_qf, 0, 1, 0 };
    ProjJob e1 { key,   Wke, bke, (float*)p_kf, 0, 1, 0 };
    proj_batch_kernel<<<dim3(4, 32, 2), 256>>>(e0, e1, e0, e0, EE);

    // stage-2 projections
    ProjJob s0 { (const float*)p_qf, W1,  nullptr, (float*)p_qp,  0,   0, 0 };
    ProjJob s1 { (const float*)p_kf, W1,  nullptr, (float*)p_kpT, 256, 0, 1 };
    ProjJob s2 { (const float*)p_qf, Wv1, nullptr, (float*)p_vq,  0,   0, 0 };
    ProjJob s3 { (const float*)p_kf, Wv1, nullptr, (float*)p_vkT, 256, 0, 1 };
    proj_batch_kernel<<<dim3(4, 32, 4), 256>>>(s0, s1, s2, s3, HH);

    // main fused pairwise-MLP kernel (mma.sync fp16, reg-pipelined)
    cudaFuncSetAttribute(pair_mma_kernel,
                         cudaFuncAttributeMaxDynamicSharedMemorySize, SMEM_BYTES);
    pair_mma_kernel<<<BB * SQ * (SKK / 128), 512, SMEM_BYTES>>>(
        b1, b2, b3, Wf, bf, bv1, Wv2, bv2, out);
}

// round 9
// speedup vs baseline: 5.4550x; 1.0626x over previous
#include <cuda_runtime.h>
#include <cuda_bf16.h>
#include <cuda_fp16.h>
#include <math.h>
#include <stdint.h>

// Problem dims (fixed)
#define BB   2
#define SQ   512
#define SKK  512
#define EE   512
#define HH   256
#define MR   1024            // B*SQ = B*SK
#define NTOT (BB*SQ*SKK)     // 524288

// ---------------- scratch (device globals; no allocation allowed) -------------
__device__ float g_qf [MR*HH];
__device__ float g_kf [MR*HH];
__device__ float g_qp [MR*HH];
__device__ float g_vq [MR*HH];
__device__ float g_kpT[HH*MR];   // [H][B*SK]
__device__ float g_vkT[HH*MR];   // [H][B*SK]
// fp16 weight images: word layout [layer][k][nw] (nw = n/2, f16x2)
__device__ __align__(16) uint32_t g_Wh[2 * 256 * 128];

// SMEM map (byte offsets from 1024-aligned base)
#define SM_A   0u        // 128 rows x 512B  (fp16 A)
#define SM_W   65536u    // 256 rows x 512B  (full weight layer, fp16)
#define SM_VEC 196608u
#define SMEM_BYTES (206848 + 1024)

// ---------------- PTX helpers --------------------------------------------------
__device__ __forceinline__ uint32_t smem_u32(const void* p) {
    return (uint32_t)__cvta_generic_to_shared(p);
}
__device__ __forceinline__ void ldsm_x4(uint32_t (&r)[4], uint32_t addr) {
    asm volatile("ldmatrix.sync.aligned.m8n8.x4.shared.b16 {%0,%1,%2,%3}, [%4];"
        : "=r"(r[0]), "=r"(r[1]), "=r"(r[2]), "=r"(r[3]) : "r"(addr));
}
__device__ __forceinline__ void ldsm_x4_t(uint32_t (&r)[4], uint32_t addr) {
    asm volatile("ldmatrix.sync.aligned.m8n8.x4.trans.shared.b16 {%0,%1,%2,%3}, [%4];"
        : "=r"(r[0]), "=r"(r[1]), "=r"(r[2]), "=r"(r[3]) : "r"(addr));
}
__device__ __forceinline__ void mma_f16(float (&d)[4], const uint32_t (&a)[4],
                                        uint32_t b0, uint32_t b1) {
    asm volatile("mma.sync.aligned.m16n8k16.row.col.f32.f16.f16.f32 "
        "{%0,%1,%2,%3}, {%4,%5,%6,%7}, {%8,%9}, {%0,%1,%2,%3};"
        : "+f"(d[0]), "+f"(d[1]), "+f"(d[2]), "+f"(d[3])
        : "r"(a[0]), "r"(a[1]), "r"(a[2]), "r"(a[3]), "r"(b0), "r"(b1));
}
__device__ __forceinline__ unsigned long long pack_dup(float a) {
    unsigned long long r;
    asm("mov.b64 %0, {%1, %1};" : "=l"(r) : "f"(a));
    return r;
}
__device__ __forceinline__ void unpack2(unsigned long long v, float& lo, float& hi) {
    asm("mov.b64 {%0, %1}, %2;" : "=f"(lo), "=f"(hi) : "l"(v));
}
__device__ __forceinline__ void ffma2(unsigned long long& acc, unsigned long long a,
                                      unsigned long long b) {
    asm("fma.rn.f32x2 %0, %1, %2, %0;" : "+l"(acc) : "l"(a), "l"(b));
}

// ---------------- small math helpers ------------------------------------------
// pack two floats as f16x2 (v0 -> low half, v1 -> high half)
__device__ __forceinline__ uint32_t f16x2bits(float v0, float v1) {
    __half2 h = __floats2half2_rn(v0, v1);
    return *reinterpret_cast<uint32_t*>(&h);
}
__device__ __forceinline__ float softplusf(float x) {
    if (x > 20.f) return x;
    return log1pf(expf(x));
}

// ---------------- weight convert prologue (fp16) -------------------------------
__global__ __launch_bounds__(256)
void wsplit_kernel(const float* __restrict__ W2, const float* __restrict__ W3)
{
    int idx = blockIdx.x * 256 + threadIdx.x;     // 0..65535
    int layer = idx >> 15;
    int rem   = idx & 32767;
    int k  = rem >> 7;          // 0..255
    int nw = rem & 127;         // 0..127
    const float* W = layer ? W3 : W2;
    float v0 = W[k * 256 + nw * 2];
    float v1 = W[k * 256 + nw * 2 + 1];
    g_Wh[idx] = f16x2bits(v0, v1);
}

// ---------------- prologue: batched 1024x256 projection GEMM (f32x2) ----------
struct ProjJob {
    const float* A; const float* W; const float* bias; float* C;
    int wrow0; int doRelu; int doTrans;
};

__global__ __launch_bounds__(256)
void proj_batch_kernel(ProjJob j0, ProjJob j1, ProjJob j2, ProjJob j3, int K)
{
    ProjJob jb = (blockIdx.z == 0) ? j0 : (blockIdx.z == 1) ? j1 :
                 (blockIdx.z == 2) ? j2 : j3;
    __shared__ float As[16][36];
    __shared__ float Ws[16][68];
    const int tid = threadIdx.x;
    const int m0  = blockIdx.y * 32;
    const int n0  = blockIdx.x * 64;
    const int ty  = tid >> 4, tx = tid & 15;

    unsigned long long acc2[2][2] = {{0ull, 0ull}, {0ull, 0ull}};
    const int nch = K >> 4;
    for (int ch = 0; ch < nch; ch++) {
        const int kc = ch << 4;
        __syncthreads();
        {
            int e = tid;        int m = e >> 4, kk = e & 15;
            As[kk][m] = jb.A[(m0 + m) * K + kc + kk];
            e = tid + 256;      m = e >> 4;     kk = e & 15;
            As[kk][m] = jb.A[(m0 + m) * K + kc + kk];
        }
        #pragma unroll
        for (int i = 0; i < 4; i++) {
            int e = tid + (i << 8);
            int kk = e >> 6, n = e & 63;
            Ws[kk][n] = jb.W[(jb.wrow0 + kc + kk) * 256 + n0 + n];
        }
        __syncthreads();
        #pragma unroll
        for (int kk = 0; kk < 16; kk++) {
            unsigned long long a0d = pack_dup(As[kk][ty * 2]);
            unsigned long long a1d = pack_dup(As[kk][ty * 2 + 1]);
            unsigned long long w01 = *(const unsigned long long*)&Ws[kk][tx * 4];
            unsigned long long w23 = *(const unsigned long long*)&Ws[kk][tx * 4 + 2];
            ffma2(acc2[0][0], a0d, w01);
            ffma2(acc2[0][1], a0d, w23);
            ffma2(acc2[1][0], a1d, w01);
            ffma2(acc2[1][1], a1d, w23);
        }
    }
    #pragma unroll
    for (int i = 0; i < 2; i++) {
        float vout[4];
        unpack2(acc2[i][0], vout[0], vout[1]);
        unpack2(acc2[i][1], vout[2], vout[3]);
        const int r = m0 + ty * 2 + i;
        #pragma unroll
        for (int j = 0; j < 4; j++) {
            const int n = n0 + tx * 4 + j;
            float v = vout[j] + (jb.bias ? jb.bias[n] : 0.f);
            if (jb.doRelu) v = fmaxf(v, 0.f);
            if (jb.doTrans) jb.C[n * MR + r] = v;
            else            jb.C[r * 256 + n] = v;
        }
    }
}

// ---------------- main pairwise-MLP kernel (mma.sync fp16, barrier-free GEMM) --

// copy one full weight layer (128KB, 256 rows x 512B) into SM_W with swizzle
__device__ __forceinline__ void cp_layer(const char* __restrict__ src,
                                         uint32_t dstbase, int tid)
{
    #pragma unroll
    for (int i = 0; i < 16; i++) {
        int e = tid + i * 512;                 // 0..8191
        int k = e >> 5, u = e & 31;            // row (0..255), 16B unit
        uint32_t d = dstbase + (uint32_t)k * 512u + (uint32_t)((u ^ (k & 7)) << 4);
        asm volatile("cp.async.cg.shared.global [%0], [%1], 16;"
                     :: "r"(d), "l"(src + e * 16));
    }
    asm volatile("cp.async.commit_group;" ::: "memory");
}

// build 2 adjacent 16B units (g0, g0+1) of one A row: j0 = 8*g0 + quad*2
__device__ __forceinline__ void a_store_units(char* smp, int m, int quad, int g0,
                                              float v0, float v1, float v2, float v3)
{
    char* arow = smp + (uint32_t)m * 512u;
    uint32_t off0 = (uint32_t)(((g0 ^ (m & 7)) << 4) + quad * 4);
    *(uint32_t*)(arow + SM_A + off0) = f16x2bits(v0, v1);
    uint32_t off1 = (uint32_t)((((g0 + 1) ^ (m & 7)) << 4) + quad * 4);
    *(uint32_t*)(arow + SM_A + off1) = f16x2bits(v2, v3);
}

// One 128x256x256 fp16 GEMM: acc += A(smem) @ W(smem, full layer resident).
// Register-pipelined fragments; NO barriers, NO waits — pure MMA stream.
__device__ __forceinline__ void gemm_pass(uint32_t abase,
                                          int warpM, int warpN, int lane,
                                          float (&acc)[2][8][4])
{
    const int rit  = (lane & 7) | (((lane >> 3) & 1) << 3); // row within 16-tile
    const int koff = lane >> 4;                              // 0/1: unit select
    uint32_t a_row[2]; uint32_t a_sw[2];
    #pragma unroll
    for (int mt = 0; mt < 2; mt++) {
        int rr = warpM * 32 + mt * 16 + rit;
        a_row[mt] = abase + (uint32_t)rr * 512u;
        a_sw[mt]  = (uint32_t)(rr & 7);
    }
    const uint32_t ksw = (uint32_t)(rit & 7);
    uint32_t boff[4];
    #pragma unroll
    for (int np = 0; np < 4; np++) {
        uint32_t nunit = (uint32_t)(warpN * 8 + np * 2 + koff);
        boff[np] = ((nunit ^ ksw) << 4);
    }
    const uint32_t browbase = abase + SM_W + (uint32_t)rit * 512u;

    // fragment double buffers: parity = k16 & 1
    uint32_t aF[2][2][4];   // [parity][mt]
    uint32_t bF[2][2][4];   // [parity][np 0..1]
    #pragma unroll
    for (int mt = 0; mt < 2; mt++)
        ldsm_x4(aF[0][mt], a_row[mt] + (((uint32_t)koff ^ a_sw[mt]) << 4));
    ldsm_x4_t(bF[0][0], browbase + boff[0]);
    ldsm_x4_t(bF[0][1], browbase + boff[1]);

    #pragma unroll
    for (int k16 = 0; k16 < 16; k16++) {
        const int s = k16 & 1;
        uint32_t bT[2][4];
        const uint32_t brow = browbase + (uint32_t)k16 * 8192u;
        ldsm_x4_t(bT[0], brow + boff[2]);
        ldsm_x4_t(bT[1], brow + boff[3]);

        #pragma unroll
        for (int mt = 0; mt < 2; mt++) {
            mma_f16(acc[mt][0], aF[s][mt], bF[s][0][0], bF[s][0][1]);
            mma_f16(acc[mt][1], aF[s][mt], bF[s][0][2], bF[s][0][3]);
            mma_f16(acc[mt][2], aF[s][mt], bF[s][1][0], bF[s][1][1]);
            mma_f16(acc[mt][3], aF[s][mt], bF[s][1][2], bF[s][1][3]);
        }

        if (k16 < 15) {
            #pragma unroll
            for (int mt = 0; mt < 2; mt++) {
                uint32_t unit = (uint32_t)((k16 + 1) * 2 + koff);
                ldsm_x4(aF[s ^ 1][mt], a_row[mt] + ((unit ^ a_sw[mt]) << 4));
            }
            const uint32_t brown = browbase + (uint32_t)(k16 + 1) * 8192u;
            ldsm_x4_t(bF[s ^ 1][0], brown + boff[0]);
            ldsm_x4_t(bF[s ^ 1][1], brown + boff[1]);
        }

        #pragma unroll
        for (int mt = 0; mt < 2; mt++) {
            mma_f16(acc[mt][4], aF[s][mt], bT[0][0], bT[0][1]);
            mma_f16(acc[mt][5], aF[s][mt], bT[0][2], bT[0][3]);
            mma_f16(acc[mt][6], aF[s][mt], bT[1][0], bT[1][1]);
            mma_f16(acc[mt][7], aF[s][mt], bT[1][2], bT[1][3]);
        }
    }
}

__global__ __launch_bounds__(512, 1)
void pair_mma_kernel(const float* __restrict__ b1,  const float* __restrict__ b2,
                     const float* __restrict__ b3,  const float* __restrict__ Wf,
                     const float* __restrict__ bfp, const float* __restrict__ bv1,
                     const float* __restrict__ Wv2, const float* __restrict__ bv2,
                     float* __restrict__ out)
{
    extern __shared__ char smraw[];
    const uint32_t smbase = smem_u32(smraw);
    const uint32_t abase  = (smbase + 1023u) & ~1023u;
    char* smp = smraw + (abase - smbase);
    float* qpb  = (float*)(smp + SM_VEC);
    float* vqb  = qpb + 256;
    float* b2s  = vqb + 256;
    float* b3s  = b2s + 256;
    float* wfs  = b3s + 256;
    float* wv2s = wfs + 256;
    float* red  = wv2s + 256;   // 512 floats: [row][warpN]
    float* vred = red + 512;    // 512 floats: [key][p]

    const int tid   = threadIdx.x;
    const int lane  = tid & 31;
    const int w     = tid >> 5;
    const int warpM = w & 3, warpN = w >> 2;
    const int quad  = tid >> 7;
    const int m     = tid & 127;
    const int bid = blockIdx.x;
    const int kt  = bid & 3;
    const int q   = (bid >> 2) & 511;
    const int b   = bid >> 11;
    const int k0  = kt << 7;
    const int rowb  = b * SKK + k0 + m;
    const int lbase = (b * SQ + q) * SKK + k0;

    // start the full W2 copy immediately (128KB, async)
    cp_layer((const char*)g_Wh, abase + SM_W, tid);

    // vectors
    {
        const int r = (b * SQ + q) * HH;
        if (tid < 256) {
            qpb[tid] = g_qp[r + tid] + b1[tid];
            b2s[tid] = b2[tid];
            wfs[tid] = Wf[tid];
        } else {
            int u = tid & 255;
            vqb[u]  = g_vq[r + u] + bv1[u];
            b3s[u]  = b3[u];
            wv2s[u] = Wv2[u];
        }
    }
    __syncthreads();

    // ---- build ALL of A (h0) + variance dot, overlapping the W2 copy ----
    {
        #pragma unroll 4
        for (int gg = 0; gg < 16; gg++) {
            int g0 = gg * 2;
            int j0 = 8 * g0 + quad * 2;
            float v0 = fmaxf(qpb[j0]     + g_kpT[j0 * MR + rowb],       0.f);
            float v1 = fmaxf(qpb[j0 + 1] + g_kpT[(j0 + 1) * MR + rowb], 0.f);
            float v2 = fmaxf(qpb[j0 + 8] + g_kpT[(j0 + 8) * MR + rowb], 0.f);
            float v3 = fmaxf(qpb[j0 + 9] + g_kpT[(j0 + 9) * MR + rowb], 0.f);
            a_store_units(smp, m, quad, g0, v0, v1, v2, v3);
        }
        float vacc = 0.f;
        #pragma unroll 8
        for (int jj = 0; jj < 64; jj++) {
            int j = quad * 64 + jj;
            vacc = fmaf(fmaxf(vqb[j] + g_vkT[j * MR + rowb], 0.f), wv2s[j], vacc);
        }
        vred[m * 4 + quad] = vacc;
    }
    asm volatile("cp.async.wait_group 0;" ::: "memory");
    __syncthreads();

    // ---- GEMM 1: D = h0 @ W2 (barrier-free) ----
    float acc[2][8][4];
    #pragma unroll
    for (int i = 0; i < 2; i++)
        #pragma unroll
        for (int j = 0; j < 8; j++)
            #pragma unroll
            for (int e = 0; e < 4; e++) acc[i][j][e] = 0.f;
    gemm_pass(abase, warpM, warpN, lane, acc);
    __syncthreads();   // all W2 + h0 reads done

    // start the full W3 copy (overlaps epilogue 1 + variance finalize)
    cp_layer((const char*)g_Wh + 131072, abase + SM_W, tid);

    // variance finalize
    if (tid < 128) {
        float s = vred[tid * 4] + vred[tid * 4 + 1] + vred[tid * 4 + 2] + vred[tid * 4 + 3]
                  + bv2[0];
        out[NTOT + lbase + tid] = softplusf(s);
    }

    // ---- epilogue 1: h1 = relu(D + b2) -> A buffer (fp16) ----
    {
        const int g  = lane >> 2;
        const int tg = lane & 3;
        #pragma unroll
        for (int mt = 0; mt < 2; mt++) {
            int r0 = warpM * 32 + mt * 16 + g;
            int r1 = r0 + 8;
            uint32_t row0 = (uint32_t)r0 * 512u;
            uint32_t row1 = (uint32_t)r1 * 512u;
            #pragma unroll
            for (int nt = 0; nt < 8; nt++) {
                int c0 = warpN * 64 + nt * 8 + tg * 2;
                float b20 = b2s[c0], b21 = b2s[c0 + 1];
                float v00 = fmaxf(acc[mt][nt][0] + b20, 0.f);
                float v01 = fmaxf(acc[mt][nt][1] + b21, 0.f);
                float v10 = fmaxf(acc[mt][nt][2] + b20, 0.f);
                float v11 = fmaxf(acc[mt][nt][3] + b21, 0.f);
                uint32_t unit = (uint32_t)(c0 >> 3);
                uint32_t o0 = row0 + ((unit ^ (uint32_t)(r0 & 7)) << 4) + (uint32_t)(tg * 4);
                uint32_t o1 = row1 + ((unit ^ (uint32_t)(r1 & 7)) << 4) + (uint32_t)(tg * 4);
                *(uint32_t*)(smp + SM_A + o0) = f16x2bits(v00, v01);
                *(uint32_t*)(smp + SM_A + o1) = f16x2bits(v10, v11);
            }
        }
    }
    asm volatile("cp.async.wait_group 0;" ::: "memory");
    __syncthreads();

    // ---- GEMM 2: D = h1 @ W3 (barrier-free) ----
    #pragma unroll
    for (int i = 0; i < 2; i++)
        #pragma unroll
        for (int j = 0; j < 8; j++)
            #pragma unroll
            for (int e = 0; e < 4; e++) acc[i][j][e] = 0.f;
    gemm_pass(abase, warpM, warpN, lane, acc);

    // ---- epilogue 2: logit = relu(D + b3) . Wf, cross-warp reduce ----
    {
        const int g  = lane >> 2;
        const int tg = lane & 3;
        #pragma unroll
        for (int mt = 0; mt < 2; mt++) {
            float lg0 = 0.f, lg1 = 0.f;
            #pragma unroll
            for (int nt = 0; nt < 8; nt++) {
                int c0 = warpN * 64 + nt * 8 + tg * 2;
                float b30 = b3s[c0], b31 = b3s[c0 + 1];
                float w0  = wfs[c0], w1  = wfs[c0 + 1];
                lg0 = fmaf(fmaxf(acc[mt][nt][0] + b30, 0.f), w0, lg0);
                lg0 = fmaf(fmaxf(acc[mt][nt][1] + b31, 0.f), w1, lg0);
                lg1 = fmaf(fmaxf(acc[mt][nt][2] + b30, 0.f), w0, lg1);
                lg1 = fmaf(fmaxf(acc[mt][nt][3] + b31, 0.f), w1, lg1);
            }
            lg0 += __shfl_xor_sync(0xffffffffu, lg0, 1);
            lg0 += __shfl_xor_sync(0xffffffffu, lg0, 2);
            lg1 += __shfl_xor_sync(0xffffffffu, lg1, 1);
            lg1 += __shfl_xor_sync(0xffffffffu, lg1, 2);
            if (tg == 0) {
                int r0 = warpM * 32 + mt * 16 + g;
                red[r0 * 4 + warpN]       = lg0;
                red[(r0 + 8) * 4 + warpN] = lg1;
            }
        }
    }
    __syncthreads();
    if (tid < 128) {
        float s = red[tid * 4] + red[tid * 4 + 1] + red[tid * 4 + 2] + red[tid * 4 + 3]
                  + bfp[0];
        out[lbase + tid] = s;
    }
}

// ---------------- launcher -----------------------------------------------------
extern "C" void kernel_launch(void* const* d_in, const int* in_sizes, int n_in,
                              void* d_out, int out_size)
{
    const float* query = (const float*)d_in[0];
    const float* key   = (const float*)d_in[1];
    const float* Wqe   = (const float*)d_in[2];
    const float* bqe   = (const float*)d_in[3];
    const float* Wke   = (const float*)d_in[4];
    const float* bke   = (const float*)d_in[5];
    const float* W1    = (const float*)d_in[6];
    const float* b1    = (const float*)d_in[7];
    const float* W2    = (const float*)d_in[8];
    const float* b2    = (const float*)d_in[9];
    const float* W3    = (const float*)d_in[10];
    const float* b3    = (const float*)d_in[11];
    const float* Wf    = (const float*)d_in[12];
    const float* bf    = (const float*)d_in[13];
    const float* Wv1   = (const float*)d_in[14];
    const float* bv1   = (const float*)d_in[15];
    const float* Wv2   = (const float*)d_in[16];
    const float* bv2   = (const float*)d_in[17];
    float* out = (float*)d_out;

    void *p_qf, *p_kf, *p_qp, *p_vq, *p_kpT, *p_vkT;
    cudaGetSymbolAddress(&p_qf,  g_qf);
    cudaGetSymbolAddress(&p_kf,  g_kf);
    cudaGetSymbolAddress(&p_qp,  g_qp);
    cudaGetSymbolAddress(&p_vq,  g_vq);
    cudaGetSymbolAddress(&p_kpT, g_kpT);
    cudaGetSymbolAddress(&p_vkT, g_vkT);

    // weight convert (independent of projections)
    wsplit_kernel<<<256, 256>>>(W2, W3);

    // encoders: qf = relu(query@Wqe+bqe), kf = relu(key@Wke+bke)
    ProjJob e0 { query, Wqe, bqe, (float*)p_qf, 0, 1, 0 };
    ProjJob e1 { key,   Wke, bke, (float*)p_kf, 0, 1, 0 };
    proj_batch_kernel<<<dim3(4, 32, 2), 256>>>(e0, e1, e0, e0, EE);

    // stage-2 projections
    ProjJob s0 { (const float*)p_qf, W1,  nullptr, (float*)p_qp,  0,   0, 0 };
    ProjJob s1 { (const float*)p_kf, W1,  nullptr, (float*)p_kpT, 256, 0, 1 };
    ProjJob s2 { (const float*)p_qf, Wv1, nullptr, (float*)p_vq,  0,   0, 0 };
    ProjJob s3 { (const float*)p_kf, Wv1, nullptr, (float*)p_vkT, 256, 0, 1 };
    proj_batch_kernel<<<dim3(4, 32, 4), 256>>>(s0, s1, s2, s3, HH);

    // main fused pairwise-MLP kernel (mma.sync fp16, barrier-free GEMMs)
    cudaFuncSetAttribute(pair_mma_kernel,
                         cudaFuncAttributeMaxDynamicSharedMemorySize, SMEM_BYTES);
    pair_mma_kernel<<<BB * SQ * (SKK / 128), 512, SMEM_BYTES>>>(
        b1, b2, b3, Wf, bf, bv1, Wv2, bv2, out);
}